// round 1
// baseline (speedup 1.0000x reference)
#include <cuda_runtime.h>
#include <math.h>

// ---------------------------------------------------------------------------
// BondUpdateLayer: fused pipeline
//   K1a: per-edge distance gaussians
//   K1b: per-edge Q MLP (hoisted out of triplet loop: q depends only on idx_ji)
//   K2 : per-triplet kv assembly + hk MLP -> logits, hv MLP -> V
//   K3 : per-edge segment softmax (idx_ji is sorted => contiguous segments)
// ---------------------------------------------------------------------------

#define EN    80000        // E = N*DEG = 10000*8 (fixed by dataset)
#define TMAXN 640000       // T <= 8*E (sum of in-degrees over sources)

__device__ float g_rfeat [EN * 20];
__device__ float g_q     [EN * 128];
__device__ float g_logits[(size_t)TMAXN * 16];
__device__ float g_v     [(size_t)TMAXN * 128];

// ---------------- K1a: edge gaussian features ----------------
__global__ void edge_feat_kernel(const float* __restrict__ pos,
                                 const int* __restrict__ brow,
                                 const int* __restrict__ bcol, int E)
{
    int e = blockIdx.x * blockDim.x + threadIdx.x;
    if (e >= E) return;
    int r = brow[e], c = bcol[e];
    float dx = pos[c*3+0] - pos[r*3+0];
    float dy = pos[c*3+1] - pos[r*3+1];
    float dz = pos[c*3+2] - pos[r*3+2];
    float d  = sqrtf(dx*dx + dy*dy + dz*dz);
    const float step  = 10.0f / 19.0f;
    const float coeff = -0.5f / (step * step);
    #pragma unroll
    for (int g = 0; g < 20; ++g) {
        float t = d - step * (float)g;
        g_rfeat[e*20 + g] = expf(coeff * t * t);
    }
}

// ---------------- shared block MLP: X[64,kdim] -> out[64,128] ----------------
// Linear(W1,b1) -> LayerNorm(gam,bet) -> ReLU -> Linear(W2,b2)
// 256 threads: tx = tid&15 (8 cols each), ty = tid>>4 (4 rows each).
__device__ __forceinline__ void block_mlp(
    const float* __restrict__ Xs, int xstride, int kpad, int kdim,
    const float* __restrict__ W1, const float* __restrict__ b1,
    const float* __restrict__ gam, const float* __restrict__ bet,
    const float* __restrict__ W2, const float* __restrict__ b2,
    float* Ws, float* Hs, float* mu_s, float* rs_s,
    int tid, int tx, int ty, float acc[4][8])
{
    float a1[4][8];
    #pragma unroll
    for (int r = 0; r < 4; r++)
        #pragma unroll
        for (int c = 0; c < 8; c++) a1[r][c] = 0.f;

    // -------- GEMM1: X @ W1 --------
    for (int k0 = 0; k0 < kpad; k0 += 32) {
        __syncthreads();
        #pragma unroll
        for (int v = tid; v < 32*32; v += 256) {       // 32 k-rows x 32 float4
            int kr = v >> 5, c4 = v & 31;
            int krow = k0 + kr;
            float4 w = make_float4(0.f, 0.f, 0.f, 0.f);
            if (krow < kdim) w = ((const float4*)W1)[krow*32 + c4];
            ((float4*)Ws)[v] = w;
        }
        __syncthreads();
        #pragma unroll 4
        for (int kk = 0; kk < 32; ++kk) {
            float av0 = Xs[(ty*4+0)*xstride + k0 + kk];
            float av1 = Xs[(ty*4+1)*xstride + k0 + kk];
            float av2 = Xs[(ty*4+2)*xstride + k0 + kk];
            float av3 = Xs[(ty*4+3)*xstride + k0 + kk];
            float4 w0 = ((float4*)Ws)[kk*32 + tx*2];
            float4 w1 = ((float4*)Ws)[kk*32 + tx*2 + 1];
            float bv[8] = {w0.x, w0.y, w0.z, w0.w, w1.x, w1.y, w1.z, w1.w};
            #pragma unroll
            for (int c = 0; c < 8; c++) {
                a1[0][c] += av0 * bv[c];
                a1[1][c] += av1 * bv[c];
                a1[2][c] += av2 * bv[c];
                a1[3][c] += av3 * bv[c];
            }
        }
    }

    // -------- bias + LayerNorm partials --------
    float* red = Ws;  // alias: 4096 floats available
    __syncthreads();
    #pragma unroll
    for (int r = 0; r < 4; r++) {
        float s = 0.f, s2 = 0.f;
        #pragma unroll
        for (int c = 0; c < 8; c++) {
            float xv = a1[r][c] + b1[tx*8 + c];
            a1[r][c] = xv;
            s += xv; s2 += xv * xv;
        }
        red[(ty*4+r)*16 + tx]        = s;
        red[1024 + (ty*4+r)*16 + tx] = s2;
    }
    __syncthreads();
    if (tid < 64) {
        float s = 0.f, s2 = 0.f;
        #pragma unroll
        for (int i = 0; i < 16; i++) { s += red[tid*16 + i]; s2 += red[1024 + tid*16 + i]; }
        float mu  = s * (1.f / 128.f);
        float var = fmaxf(s2 * (1.f / 128.f) - mu * mu, 0.f);
        mu_s[tid] = mu;
        rs_s[tid] = rsqrtf(var + 1e-5f);
    }
    __syncthreads();
    #pragma unroll
    for (int r = 0; r < 4; r++) {
        int row = ty*4 + r;
        float mu = mu_s[row], rs = rs_s[row];
        #pragma unroll
        for (int c = 0; c < 8; c++) {
            float h = gam[tx*8 + c] * (a1[r][c] - mu) * rs + bet[tx*8 + c];
            Hs[row*132 + tx*8 + c] = fmaxf(h, 0.f);
        }
    }

    // -------- GEMM2: H @ W2 --------
    #pragma unroll
    for (int r = 0; r < 4; r++)
        #pragma unroll
        for (int c = 0; c < 8; c++) acc[r][c] = 0.f;

    for (int k0 = 0; k0 < 128; k0 += 32) {
        __syncthreads();
        #pragma unroll
        for (int v = tid; v < 32*32; v += 256) {
            int kr = v >> 5, c4 = v & 31;
            ((float4*)Ws)[v] = ((const float4*)W2)[(k0 + kr)*32 + c4];
        }
        __syncthreads();
        #pragma unroll 4
        for (int kk = 0; kk < 32; ++kk) {
            float av0 = Hs[(ty*4+0)*132 + k0 + kk];
            float av1 = Hs[(ty*4+1)*132 + k0 + kk];
            float av2 = Hs[(ty*4+2)*132 + k0 + kk];
            float av3 = Hs[(ty*4+3)*132 + k0 + kk];
            float4 w0 = ((float4*)Ws)[kk*32 + tx*2];
            float4 w1 = ((float4*)Ws)[kk*32 + tx*2 + 1];
            float bv[8] = {w0.x, w0.y, w0.z, w0.w, w1.x, w1.y, w1.z, w1.w};
            #pragma unroll
            for (int c = 0; c < 8; c++) {
                acc[0][c] += av0 * bv[c];
                acc[1][c] += av1 * bv[c];
                acc[2][c] += av2 * bv[c];
                acc[3][c] += av3 * bv[c];
            }
        }
    }
    #pragma unroll
    for (int r = 0; r < 4; r++)
        #pragma unroll
        for (int c = 0; c < 8; c++) acc[r][c] += b2[tx*8 + c];
}

// ---------------- K1b: Q MLP over edges ----------------
__global__ void q_mlp_kernel(const float* __restrict__ h_bond,
    const float* __restrict__ W1, const float* __restrict__ b1,
    const float* __restrict__ gam, const float* __restrict__ bet,
    const float* __restrict__ W2, const float* __restrict__ b2, int E)
{
    extern __shared__ float sm[];
    float* Xs   = sm;                 // 64*132
    float* Hs   = Xs + 64*132;        // 64*132
    float* Ws   = Hs + 64*132;        // 4096
    float* mu_s = Ws + 4096;          // 64
    float* rs_s = mu_s + 64;          // 64
    int tid = threadIdx.x, tx = tid & 15, ty = tid >> 4;
    int e0 = blockIdx.x * 64;

    for (int v = tid; v < 64*32; v += 256) {
        int row = v >> 5, c4 = v & 31;
        float4 x = make_float4(0.f, 0.f, 0.f, 0.f);
        if (e0 + row < E) x = ((const float4*)h_bond)[(size_t)(e0 + row)*32 + c4];
        float* xr = Xs + row*132 + c4*4;
        xr[0] = x.x; xr[1] = x.y; xr[2] = x.z; xr[3] = x.w;
    }
    __syncthreads();

    float acc[4][8];
    block_mlp(Xs, 132, 128, 128, W1, b1, gam, bet, W2, b2,
              Ws, Hs, mu_s, rs_s, tid, tx, ty, acc);

    #pragma unroll
    for (int r = 0; r < 4; r++) {
        int e = e0 + ty*4 + r;
        if (e < E) {
            float4 o0 = make_float4(acc[r][0], acc[r][1], acc[r][2], acc[r][3]);
            float4 o1 = make_float4(acc[r][4], acc[r][5], acc[r][6], acc[r][7]);
            float4* qp = (float4*)(g_q + (size_t)e*128 + tx*8);
            qp[0] = o0; qp[1] = o1;
        }
    }
}

// ---------------- K2: triplet kv -> hk (logits), hv (V) ----------------
__global__ void triplet_kernel(
    const float* __restrict__ h_bond, const float* __restrict__ pos,
    const float* __restrict__ kW1, const float* __restrict__ kb1,
    const float* __restrict__ kg,  const float* __restrict__ kb,
    const float* __restrict__ kW2, const float* __restrict__ kb2,
    const float* __restrict__ vW1, const float* __restrict__ vb1,
    const float* __restrict__ vg,  const float* __restrict__ vb,
    const float* __restrict__ vW2, const float* __restrict__ vb2,
    const int* __restrict__ idx_i, const int* __restrict__ idx_j,
    const int* __restrict__ idx_k, const int* __restrict__ idx_kj,
    const int* __restrict__ idx_ji, int T)
{
    extern __shared__ float sm[];
    const int XS = 196;               // 192 data cols (padded) + 4 pad for banks
    float* Xs   = sm;                 // 64*196
    float* Hs   = Xs + 64*XS;         // 64*132
    float* Ws   = Hs + 64*132;        // 4096
    float* mu_s = Ws + 4096;          // 64
    float* rs_s = mu_s + 64;          // 64
    int*   kjS  = (int*)(rs_s + 64);  // 64
    int*   jiS  = kjS + 64;           // 64

    int tid = threadIdx.x, tx = tid & 15, ty = tid >> 4;
    int t0 = blockIdx.x * 64;

    // zero the kv tile (covers padding cols and invalid rows)
    for (int v = tid; v < 64*XS; v += 256) Xs[v] = 0.f;
    __syncthreads();

    // per-row: indices + angular features (cols 168..180)
    if (tid < 64) {
        int t = t0 + tid;
        if (t < T) {
            int kj = idx_kj[t], ji = idx_ji[t];
            kjS[tid] = kj; jiS[tid] = ji;
            int ii = idx_i[t], jj = idx_j[t], kk = idx_k[t];
            float pix = pos[ii*3+0], piy = pos[ii*3+1], piz = pos[ii*3+2];
            float jx = pos[jj*3+0]-pix, jy = pos[jj*3+1]-piy, jz = pos[jj*3+2]-piz;
            float kx = pos[kk*3+0]-pix, ky = pos[kk*3+1]-piy, kz = pos[kk*3+2]-piz;
            float dt = jx*kx + jy*ky + jz*kz;
            float cx = jy*kz - jz*ky, cy = jz*kx - jx*kz, cz = jx*ky - jy*kx;
            float cr = sqrtf(cx*cx + cy*cy + cz*cz);
            float ang = atan2f(cr, dt);
            float* xr = Xs + tid*XS + 168;
            xr[0] = ang;
            const float fq[6] = {1.f, 2.f, 3.f, 1.f, 0.5f, 1.f/3.f};
            #pragma unroll
            for (int i = 0; i < 6; i++) {
                xr[1 + i] = sinf(ang * fq[i]);
                xr[7 + i] = cosf(ang * fq[i]);
            }
        } else {
            kjS[tid] = -1; jiS[tid] = -1;
        }
    }
    __syncthreads();

    // h_bond[idx_kj] gather -> cols 0..127
    for (int v = tid; v < 64*32; v += 256) {
        int row = v >> 5, c4 = v & 31;
        int kj = kjS[row];
        if (kj >= 0) {
            float4 hb = ((const float4*)h_bond)[(size_t)kj*32 + c4];
            float* xr = Xs + row*XS + c4*4;
            xr[0] = hb.x; xr[1] = hb.y; xr[2] = hb.z; xr[3] = hb.w;
        }
    }
    // rfeat gathers -> cols 128..147 (kj), 148..167 (ji)
    for (int v = tid; v < 64*20; v += 256) {
        int row = v / 20, g = v % 20;
        int kj = kjS[row];
        if (kj >= 0) {
            Xs[row*XS + 128 + g] = g_rfeat[kj*20 + g];
            Xs[row*XS + 148 + g] = g_rfeat[jiS[row]*20 + g];
        }
    }
    __syncthreads();

    float acc[4][8];

    // -------- hk MLP -> logits --------
    block_mlp(Xs, XS, 192, 181, kW1, kb1, kg, kb, kW2, kb2,
              Ws, Hs, mu_s, rs_s, tid, tx, ty, acc);
    const float scale = 0.3535533905932738f;  // 1/sqrt(8)
    #pragma unroll
    for (int r = 0; r < 4; r++) {
        int row = ty*4 + r;
        int ji = jiS[row];
        if (ji >= 0) {
            const float4* qp = (const float4*)(g_q + (size_t)ji*128 + tx*8);
            float4 q0 = qp[0], q1 = qp[1];
            float lg = acc[r][0]*q0.x + acc[r][1]*q0.y + acc[r][2]*q0.z + acc[r][3]*q0.w
                     + acc[r][4]*q1.x + acc[r][5]*q1.y + acc[r][6]*q1.z + acc[r][7]*q1.w;
            g_logits[(size_t)(t0 + row)*16 + tx] = lg * scale;
        }
    }

    // -------- hv MLP -> V --------
    block_mlp(Xs, XS, 192, 181, vW1, vb1, vg, vb, vW2, vb2,
              Ws, Hs, mu_s, rs_s, tid, tx, ty, acc);
    #pragma unroll
    for (int r = 0; r < 4; r++) {
        int row = ty*4 + r;
        if (jiS[row] >= 0) {
            float4 o0 = make_float4(acc[r][0], acc[r][1], acc[r][2], acc[r][3]);
            float4 o1 = make_float4(acc[r][4], acc[r][5], acc[r][6], acc[r][7]);
            float4* vp = (float4*)(g_v + (size_t)(t0 + row)*128 + tx*8);
            vp[0] = o0; vp[1] = o1;
        }
    }
}

// ---------------- K3: per-edge segment softmax + weighted V sum ----------------
__global__ void attn_out_kernel(const int* __restrict__ idx_ji,
                                int T, int E, float* __restrict__ out)
{
    int warp = (blockIdx.x * blockDim.x + threadIdx.x) >> 5;
    int lane = threadIdx.x & 31;
    if (warp >= E) return;
    int e = warp;

    // idx_ji sorted ascending: binary-search segment [s, en)
    int lo = 0, hi = T;
    while (lo < hi) { int m = (lo + hi) >> 1; if (idx_ji[m] <  e)     lo = m + 1; else hi = m; }
    int s = lo;
    int hi2 = T;
    while (lo < hi2) { int m = (lo + hi2) >> 1; if (idx_ji[m] < e + 1) lo = m + 1; else hi2 = m; }
    int en = lo;

    int head = lane >> 1, half = lane & 1;

    float mx = -INFINITY;
    for (int t = s; t < en; t++) mx = fmaxf(mx, g_logits[(size_t)t*16 + head]);

    float den = 0.f;
    float ax = 0.f, ay = 0.f, az = 0.f, aw = 0.f;
    for (int t = s; t < en; t++) {
        float w = expf(g_logits[(size_t)t*16 + head] - mx);
        den += w;
        float4 v = *(const float4*)(g_v + (size_t)t*128 + head*8 + half*4);
        ax += w * v.x; ay += w * v.y; az += w * v.z; aw += w * v.w;
    }
    float inv = (en > s) ? (1.f / den) : 0.f;
    float4 o = make_float4(ax * inv, ay * inv, az * inv, aw * inv);
    *(float4*)(out + (size_t)e*128 + head*8 + half*4) = o;
}

// ---------------- launcher ----------------
extern "C" void kernel_launch(void* const* d_in, const int* in_sizes, int n_in,
                              void* d_out, int out_size)
{
    const float* h_bond = (const float*)d_in[1];
    const float* pos    = (const float*)d_in[2];
    const float* kW1 = (const float*)d_in[3];
    const float* kb1 = (const float*)d_in[4];
    const float* kg  = (const float*)d_in[5];
    const float* kb  = (const float*)d_in[6];
    const float* kW2 = (const float*)d_in[7];
    const float* kb2 = (const float*)d_in[8];
    const float* vW1 = (const float*)d_in[9];
    const float* vb1 = (const float*)d_in[10];
    const float* vg  = (const float*)d_in[11];
    const float* vb  = (const float*)d_in[12];
    const float* vW2 = (const float*)d_in[13];
    const float* vb2 = (const float*)d_in[14];
    const float* qW1 = (const float*)d_in[15];
    const float* qb1 = (const float*)d_in[16];
    const float* qg  = (const float*)d_in[17];
    const float* qb  = (const float*)d_in[18];
    const float* qW2 = (const float*)d_in[19];
    const float* qb2 = (const float*)d_in[20];
    const int* bond_row = (const int*)d_in[21];
    const int* bond_col = (const int*)d_in[22];
    const int* idx_i  = (const int*)d_in[23];
    const int* idx_j  = (const int*)d_in[24];
    const int* idx_k  = (const int*)d_in[25];
    const int* idx_kj = (const int*)d_in[26];
    const int* idx_ji = (const int*)d_in[27];
    int E = in_sizes[21];
    int T = in_sizes[23];

    const int SMEM_Q = (64*132 + 64*132 + 4096 + 128) * 4;               // ~84.5 KB
    const int SMEM_T = (64*196 + 64*132 + 4096 + 128) * 4 + 128 * 4;     // ~101.8 KB
    cudaFuncSetAttribute(q_mlp_kernel,   cudaFuncAttributeMaxDynamicSharedMemorySize, SMEM_Q);
    cudaFuncSetAttribute(triplet_kernel, cudaFuncAttributeMaxDynamicSharedMemorySize, SMEM_T);

    edge_feat_kernel<<<(E + 255) / 256, 256>>>(pos, bond_row, bond_col, E);
    q_mlp_kernel<<<(E + 63) / 64, 256, SMEM_Q>>>(h_bond, qW1, qb1, qg, qb, qW2, qb2, E);
    triplet_kernel<<<(T + 63) / 64, 256, SMEM_T>>>(
        h_bond, pos,
        kW1, kb1, kg, kb, kW2, kb2,
        vW1, vb1, vg, vb, vW2, vb2,
        idx_i, idx_j, idx_k, idx_kj, idx_ji, T);
    attn_out_kernel<<<(E * 32 + 255) / 256, 256>>>(idx_ji, T, E, (float*)d_out);
}

// round 3
// speedup vs baseline: 1.0872x; 1.0872x over previous
#include <cuda_runtime.h>
#include <math.h>

// ---------------------------------------------------------------------------
// BondUpdateLayer: fused pipeline
//   K1a: per-edge distance gaussians
//   K1b: per-edge Q MLP (hoisted out of triplet loop)
//   K2 : per-triplet kv assembly + hk MLP -> logits, hv MLP -> V
//   K3 : per-edge segment softmax (idx_ji sorted => contiguous segments)
// Round 3: FFMA2 (fma.rn.f32x2) with FIXED weight indexing (kk*32, was kk*16).
// ---------------------------------------------------------------------------

#define EN    80000
#define TMAXN 640000

typedef unsigned long long ull;

__device__ float g_rfeat [EN * 20];
__device__ float g_q     [EN * 128];
__device__ float g_logits[(size_t)TMAXN * 16];
__device__ float g_v     [(size_t)TMAXN * 128];

__device__ __forceinline__ ull pack2(float v) {
    ull r;
    asm("mov.b64 %0, {%1, %1};" : "=l"(r) : "f"(v));
    return r;
}
__device__ __forceinline__ void fma2(ull& d, ull a, ull b) {
    asm("fma.rn.f32x2 %0, %1, %2, %0;" : "+l"(d) : "l"(a), "l"(b));
}
__device__ __forceinline__ float2 unpack2(ull v) {
    float lo, hi;
    asm("mov.b64 {%0, %1}, %2;" : "=f"(lo), "=f"(hi) : "l"(v));
    return make_float2(lo, hi);
}

// ---------------- K1a: edge gaussian features ----------------
__global__ void edge_feat_kernel(const float* __restrict__ pos,
                                 const int* __restrict__ brow,
                                 const int* __restrict__ bcol, int E)
{
    int e = blockIdx.x * blockDim.x + threadIdx.x;
    if (e >= E) return;
    int r = brow[e], c = bcol[e];
    float dx = pos[c*3+0] - pos[r*3+0];
    float dy = pos[c*3+1] - pos[r*3+1];
    float dz = pos[c*3+2] - pos[r*3+2];
    float d  = sqrtf(dx*dx + dy*dy + dz*dz);
    const float step  = 10.0f / 19.0f;
    const float coeff = -0.5f / (step * step);
    #pragma unroll
    for (int g = 0; g < 20; ++g) {
        float t = d - step * (float)g;
        g_rfeat[e*20 + g] = expf(coeff * t * t);
    }
}

// ---------------- shared block MLP: X[64,kdim] -> out[64,128] ----------------
// Linear(W1,b1) -> LayerNorm(gam,bet) -> ReLU -> Linear(W2,b2)
// 256 threads: tx = tid&15 (8 cols each), ty = tid>>4 (4 rows each).
// Accumulators packed as f32x2 column pairs, FMAs via fma.rn.f32x2.
__device__ __forceinline__ void block_mlp(
    const float* __restrict__ Xs, int xstride, int kpad, int kdim,
    const float* __restrict__ W1, const float* __restrict__ b1,
    const float* __restrict__ gam, const float* __restrict__ bet,
    const float* __restrict__ W2, const float* __restrict__ b2,
    float* Ws, float* Hs, float* mu_s, float* rs_s,
    int tid, int tx, int ty, float acc[4][8])
{
    ull a1p[4][4];
    #pragma unroll
    for (int r = 0; r < 4; r++)
        #pragma unroll
        for (int c = 0; c < 4; c++) a1p[r][c] = 0ULL;

    // -------- GEMM1: X @ W1 --------
    for (int k0 = 0; k0 < kpad; k0 += 32) {
        __syncthreads();
        #pragma unroll
        for (int v = tid; v < 32*32; v += 256) {       // 32 k-rows x 32 float4
            int kr = v >> 5, c4 = v & 31;
            int krow = k0 + kr;
            float4 w = make_float4(0.f, 0.f, 0.f, 0.f);
            if (krow < kdim) w = ((const float4*)W1)[krow*32 + c4];
            ((float4*)Ws)[v] = w;
        }
        __syncthreads();
        #pragma unroll 8
        for (int kk = 0; kk < 32; ++kk) {
            ull ap0 = pack2(Xs[(ty*4+0)*xstride + k0 + kk]);
            ull ap1 = pack2(Xs[(ty*4+1)*xstride + k0 + kk]);
            ull ap2 = pack2(Xs[(ty*4+2)*xstride + k0 + kk]);
            ull ap3 = pack2(Xs[(ty*4+3)*xstride + k0 + kk]);
            ulonglong2 w0 = ((const ulonglong2*)Ws)[kk*32 + tx*2];
            ulonglong2 w1 = ((const ulonglong2*)Ws)[kk*32 + tx*2 + 1];
            fma2(a1p[0][0], ap0, w0.x); fma2(a1p[0][1], ap0, w0.y);
            fma2(a1p[0][2], ap0, w1.x); fma2(a1p[0][3], ap0, w1.y);
            fma2(a1p[1][0], ap1, w0.x); fma2(a1p[1][1], ap1, w0.y);
            fma2(a1p[1][2], ap1, w1.x); fma2(a1p[1][3], ap1, w1.y);
            fma2(a1p[2][0], ap2, w0.x); fma2(a1p[2][1], ap2, w0.y);
            fma2(a1p[2][2], ap2, w1.x); fma2(a1p[2][3], ap2, w1.y);
            fma2(a1p[3][0], ap3, w0.x); fma2(a1p[3][1], ap3, w0.y);
            fma2(a1p[3][2], ap3, w1.x); fma2(a1p[3][3], ap3, w1.y);
        }
    }

    // -------- bias + LayerNorm partials --------
    float a1[4][8];
    float* red = Ws;  // alias: 4096 floats available
    __syncthreads();
    #pragma unroll
    for (int r = 0; r < 4; r++) {
        float s = 0.f, s2 = 0.f;
        #pragma unroll
        for (int cp = 0; cp < 4; cp++) {
            float2 t = unpack2(a1p[r][cp]);
            float x0 = t.x + b1[tx*8 + cp*2];
            float x1 = t.y + b1[tx*8 + cp*2 + 1];
            a1[r][cp*2]   = x0;
            a1[r][cp*2+1] = x1;
            s += x0 + x1; s2 += x0*x0 + x1*x1;
        }
        red[(ty*4+r)*16 + tx]        = s;
        red[1024 + (ty*4+r)*16 + tx] = s2;
    }
    __syncthreads();
    if (tid < 64) {
        float s = 0.f, s2 = 0.f;
        #pragma unroll
        for (int i = 0; i < 16; i++) { s += red[tid*16 + i]; s2 += red[1024 + tid*16 + i]; }
        float mu  = s * (1.f / 128.f);
        float var = fmaxf(s2 * (1.f / 128.f) - mu * mu, 0.f);
        mu_s[tid] = mu;
        rs_s[tid] = rsqrtf(var + 1e-5f);
    }
    __syncthreads();
    #pragma unroll
    for (int r = 0; r < 4; r++) {
        int row = ty*4 + r;
        float mu = mu_s[row], rs = rs_s[row];
        #pragma unroll
        for (int c = 0; c < 8; c++) {
            float h = gam[tx*8 + c] * (a1[r][c] - mu) * rs + bet[tx*8 + c];
            Hs[row*132 + tx*8 + c] = fmaxf(h, 0.f);
        }
    }

    // -------- GEMM2: H @ W2 --------
    ull acc2[4][4];
    #pragma unroll
    for (int r = 0; r < 4; r++)
        #pragma unroll
        for (int c = 0; c < 4; c++) acc2[r][c] = 0ULL;

    for (int k0 = 0; k0 < 128; k0 += 32) {
        __syncthreads();
        #pragma unroll
        for (int v = tid; v < 32*32; v += 256) {
            int kr = v >> 5, c4 = v & 31;
            ((float4*)Ws)[v] = ((const float4*)W2)[(k0 + kr)*32 + c4];
        }
        __syncthreads();
        #pragma unroll 8
        for (int kk = 0; kk < 32; ++kk) {
            ull ap0 = pack2(Hs[(ty*4+0)*132 + k0 + kk]);
            ull ap1 = pack2(Hs[(ty*4+1)*132 + k0 + kk]);
            ull ap2 = pack2(Hs[(ty*4+2)*132 + k0 + kk]);
            ull ap3 = pack2(Hs[(ty*4+3)*132 + k0 + kk]);
            ulonglong2 w0 = ((const ulonglong2*)Ws)[kk*32 + tx*2];
            ulonglong2 w1 = ((const ulonglong2*)Ws)[kk*32 + tx*2 + 1];
            fma2(acc2[0][0], ap0, w0.x); fma2(acc2[0][1], ap0, w0.y);
            fma2(acc2[0][2], ap0, w1.x); fma2(acc2[0][3], ap0, w1.y);
            fma2(acc2[1][0], ap1, w0.x); fma2(acc2[1][1], ap1, w0.y);
            fma2(acc2[1][2], ap1, w1.x); fma2(acc2[1][3], ap1, w1.y);
            fma2(acc2[2][0], ap2, w0.x); fma2(acc2[2][1], ap2, w0.y);
            fma2(acc2[2][2], ap2, w1.x); fma2(acc2[2][3], ap2, w1.y);
            fma2(acc2[3][0], ap3, w0.x); fma2(acc2[3][1], ap3, w0.y);
            fma2(acc2[3][2], ap3, w1.x); fma2(acc2[3][3], ap3, w1.y);
        }
    }
    #pragma unroll
    for (int r = 0; r < 4; r++)
        #pragma unroll
        for (int cp = 0; cp < 4; cp++) {
            float2 t = unpack2(acc2[r][cp]);
            acc[r][cp*2]   = t.x + b2[tx*8 + cp*2];
            acc[r][cp*2+1] = t.y + b2[tx*8 + cp*2 + 1];
        }
}

// ---------------- K1b: Q MLP over edges ----------------
__global__ void __launch_bounds__(256, 2) q_mlp_kernel(const float* __restrict__ h_bond,
    const float* __restrict__ W1, const float* __restrict__ b1,
    const float* __restrict__ gam, const float* __restrict__ bet,
    const float* __restrict__ W2, const float* __restrict__ b2, int E)
{
    extern __shared__ float sm[];
    float* Xs   = sm;                 // 64*132
    float* Hs   = Xs + 64*132;        // 64*132
    float* Ws   = Hs + 64*132;        // 4096
    float* mu_s = Ws + 4096;          // 64
    float* rs_s = mu_s + 64;          // 64
    int tid = threadIdx.x, tx = tid & 15, ty = tid >> 4;
    int e0 = blockIdx.x * 64;

    for (int v = tid; v < 64*32; v += 256) {
        int row = v >> 5, c4 = v & 31;
        float4 x = make_float4(0.f, 0.f, 0.f, 0.f);
        if (e0 + row < E) x = ((const float4*)h_bond)[(size_t)(e0 + row)*32 + c4];
        float* xr = Xs + row*132 + c4*4;
        xr[0] = x.x; xr[1] = x.y; xr[2] = x.z; xr[3] = x.w;
    }
    __syncthreads();

    float acc[4][8];
    block_mlp(Xs, 132, 128, 128, W1, b1, gam, bet, W2, b2,
              Ws, Hs, mu_s, rs_s, tid, tx, ty, acc);

    #pragma unroll
    for (int r = 0; r < 4; r++) {
        int e = e0 + ty*4 + r;
        if (e < E) {
            float4 o0 = make_float4(acc[r][0], acc[r][1], acc[r][2], acc[r][3]);
            float4 o1 = make_float4(acc[r][4], acc[r][5], acc[r][6], acc[r][7]);
            float4* qp = (float4*)(g_q + (size_t)e*128 + tx*8);
            qp[0] = o0; qp[1] = o1;
        }
    }
}

// ---------------- K2: triplet kv -> hk (logits), hv (V) ----------------
__global__ void __launch_bounds__(256, 2) triplet_kernel(
    const float* __restrict__ h_bond, const float* __restrict__ pos,
    const float* __restrict__ kW1, const float* __restrict__ kb1,
    const float* __restrict__ kg,  const float* __restrict__ kb,
    const float* __restrict__ kW2, const float* __restrict__ kb2,
    const float* __restrict__ vW1, const float* __restrict__ vb1,
    const float* __restrict__ vg,  const float* __restrict__ vb,
    const float* __restrict__ vW2, const float* __restrict__ vb2,
    const int* __restrict__ idx_i, const int* __restrict__ idx_j,
    const int* __restrict__ idx_k, const int* __restrict__ idx_kj,
    const int* __restrict__ idx_ji, int T)
{
    extern __shared__ float sm[];
    const int XS = 196;               // 192 data cols (padded) + 4 pad for banks
    float* Xs   = sm;                 // 64*196
    float* Hs   = Xs + 64*XS;         // 64*132
    float* Ws   = Hs + 64*132;        // 4096
    float* mu_s = Ws + 4096;          // 64
    float* rs_s = mu_s + 64;          // 64
    int*   kjS  = (int*)(rs_s + 64);  // 64
    int*   jiS  = kjS + 64;           // 64

    int tid = threadIdx.x, tx = tid & 15, ty = tid >> 4;
    int t0 = blockIdx.x * 64;

    // zero the kv tile (covers padding cols and invalid rows)
    for (int v = tid; v < 64*XS; v += 256) Xs[v] = 0.f;
    __syncthreads();

    // per-row: indices + angular features (cols 168..180)
    if (tid < 64) {
        int t = t0 + tid;
        if (t < T) {
            int kj = idx_kj[t], ji = idx_ji[t];
            kjS[tid] = kj; jiS[tid] = ji;
            int ii = idx_i[t], jj = idx_j[t], kk = idx_k[t];
            float pix = pos[ii*3+0], piy = pos[ii*3+1], piz = pos[ii*3+2];
            float jx = pos[jj*3+0]-pix, jy = pos[jj*3+1]-piy, jz = pos[jj*3+2]-piz;
            float kx = pos[kk*3+0]-pix, ky = pos[kk*3+1]-piy, kz = pos[kk*3+2]-piz;
            float dt = jx*kx + jy*ky + jz*kz;
            float cx = jy*kz - jz*ky, cy = jz*kx - jx*kz, cz = jx*ky - jy*kx;
            float cr = sqrtf(cx*cx + cy*cy + cz*cz);
            float ang = atan2f(cr, dt);
            float* xr = Xs + tid*XS + 168;
            xr[0] = ang;
            const float fq[6] = {1.f, 2.f, 3.f, 1.f, 0.5f, 1.f/3.f};
            #pragma unroll
            for (int i = 0; i < 6; i++) {
                xr[1 + i] = sinf(ang * fq[i]);
                xr[7 + i] = cosf(ang * fq[i]);
            }
        } else {
            kjS[tid] = -1; jiS[tid] = -1;
        }
    }
    __syncthreads();

    // h_bond[idx_kj] gather -> cols 0..127
    for (int v = tid; v < 64*32; v += 256) {
        int row = v >> 5, c4 = v & 31;
        int kj = kjS[row];
        if (kj >= 0) {
            float4 hb = ((const float4*)h_bond)[(size_t)kj*32 + c4];
            float* xr = Xs + row*XS + c4*4;
            xr[0] = hb.x; xr[1] = hb.y; xr[2] = hb.z; xr[3] = hb.w;
        }
    }
    // rfeat gathers -> cols 128..147 (kj), 148..167 (ji)
    for (int v = tid; v < 64*20; v += 256) {
        int row = v / 20, g = v % 20;
        int kj = kjS[row];
        if (kj >= 0) {
            Xs[row*XS + 128 + g] = g_rfeat[kj*20 + g];
            Xs[row*XS + 148 + g] = g_rfeat[jiS[row]*20 + g];
        }
    }
    __syncthreads();

    float acc[4][8];

    // -------- hk MLP -> logits --------
    block_mlp(Xs, XS, 192, 181, kW1, kb1, kg, kb, kW2, kb2,
              Ws, Hs, mu_s, rs_s, tid, tx, ty, acc);
    const float scale = 0.3535533905932738f;  // 1/sqrt(8)
    #pragma unroll
    for (int r = 0; r < 4; r++) {
        int row = ty*4 + r;
        int ji = jiS[row];
        if (ji >= 0) {
            const float4* qp = (const float4*)(g_q + (size_t)ji*128 + tx*8);
            float4 q0 = qp[0], q1 = qp[1];
            float lg = acc[r][0]*q0.x + acc[r][1]*q0.y + acc[r][2]*q0.z + acc[r][3]*q0.w
                     + acc[r][4]*q1.x + acc[r][5]*q1.y + acc[r][6]*q1.z + acc[r][7]*q1.w;
            g_logits[(size_t)(t0 + row)*16 + tx] = lg * scale;
        }
    }

    // -------- hv MLP -> V --------
    block_mlp(Xs, XS, 192, 181, vW1, vb1, vg, vb, vW2, vb2,
              Ws, Hs, mu_s, rs_s, tid, tx, ty, acc);
    #pragma unroll
    for (int r = 0; r < 4; r++) {
        int row = ty*4 + r;
        if (jiS[row] >= 0) {
            float4 o0 = make_float4(acc[r][0], acc[r][1], acc[r][2], acc[r][3]);
            float4 o1 = make_float4(acc[r][4], acc[r][5], acc[r][6], acc[r][7]);
            float4* vp = (float4*)(g_v + (size_t)(t0 + row)*128 + tx*8);
            vp[0] = o0; vp[1] = o1;
        }
    }
}

// ---------------- K3: per-edge segment softmax + weighted V sum ----------------
__global__ void attn_out_kernel(const int* __restrict__ idx_ji,
                                int T, int E, float* __restrict__ out)
{
    int warp = (blockIdx.x * blockDim.x + threadIdx.x) >> 5;
    int lane = threadIdx.x & 31;
    if (warp >= E) return;
    int e = warp;

    // idx_ji sorted ascending: binary-search segment [s, en)
    int lo = 0, hi = T;
    while (lo < hi) { int m = (lo + hi) >> 1; if (idx_ji[m] <  e)     lo = m + 1; else hi = m; }
    int s = lo;
    int hi2 = T;
    while (lo < hi2) { int m = (lo + hi2) >> 1; if (idx_ji[m] < e + 1) lo = m + 1; else hi2 = m; }
    int en = lo;

    int head = lane >> 1, half = lane & 1;

    float mx = -INFINITY;
    for (int t = s; t < en; t++) mx = fmaxf(mx, g_logits[(size_t)t*16 + head]);

    float den = 0.f;
    float ax = 0.f, ay = 0.f, az = 0.f, aw = 0.f;
    for (int t = s; t < en; t++) {
        float w = expf(g_logits[(size_t)t*16 + head] - mx);
        den += w;
        float4 v = *(const float4*)(g_v + (size_t)t*128 + head*8 + half*4);
        ax += w * v.x; ay += w * v.y; az += w * v.z; aw += w * v.w;
    }
    float inv = (en > s) ? (1.f / den) : 0.f;
    float4 o = make_float4(ax * inv, ay * inv, az * inv, aw * inv);
    *(float4*)(out + (size_t)e*128 + head*8 + half*4) = o;
}

// ---------------- launcher ----------------
extern "C" void kernel_launch(void* const* d_in, const int* in_sizes, int n_in,
                              void* d_out, int out_size)
{
    const float* h_bond = (const float*)d_in[1];
    const float* pos    = (const float*)d_in[2];
    const float* kW1 = (const float*)d_in[3];
    const float* kb1 = (const float*)d_in[4];
    const float* kg  = (const float*)d_in[5];
    const float* kb  = (const float*)d_in[6];
    const float* kW2 = (const float*)d_in[7];
    const float* kb2 = (const float*)d_in[8];
    const float* vW1 = (const float*)d_in[9];
    const float* vb1 = (const float*)d_in[10];
    const float* vg  = (const float*)d_in[11];
    const float* vb  = (const float*)d_in[12];
    const float* vW2 = (const float*)d_in[13];
    const float* vb2 = (const float*)d_in[14];
    const float* qW1 = (const float*)d_in[15];
    const float* qb1 = (const float*)d_in[16];
    const float* qg  = (const float*)d_in[17];
    const float* qb  = (const float*)d_in[18];
    const float* qW2 = (const float*)d_in[19];
    const float* qb2 = (const float*)d_in[20];
    const int* bond_row = (const int*)d_in[21];
    const int* bond_col = (const int*)d_in[22];
    const int* idx_i  = (const int*)d_in[23];
    const int* idx_j  = (const int*)d_in[24];
    const int* idx_k  = (const int*)d_in[25];
    const int* idx_kj = (const int*)d_in[26];
    const int* idx_ji = (const int*)d_in[27];
    int E = in_sizes[21];
    int T = in_sizes[23];

    const int SMEM_Q = (64*132 + 64*132 + 4096 + 128) * 4;               // ~84.5 KB
    const int SMEM_T = (64*196 + 64*132 + 4096 + 128) * 4 + 128 * 4;     // ~101.8 KB
    cudaFuncSetAttribute(q_mlp_kernel,   cudaFuncAttributeMaxDynamicSharedMemorySize, SMEM_Q);
    cudaFuncSetAttribute(triplet_kernel, cudaFuncAttributeMaxDynamicSharedMemorySize, SMEM_T);

    edge_feat_kernel<<<(E + 255) / 256, 256>>>(pos, bond_row, bond_col, E);
    q_mlp_kernel<<<(E + 63) / 64, 256, SMEM_Q>>>(h_bond, qW1, qb1, qg, qb, qW2, qb2, E);
    triplet_kernel<<<(T + 63) / 64, 256, SMEM_T>>>(
        h_bond, pos,
        kW1, kb1, kg, kb, kW2, kb2,
        vW1, vb1, vg, vb, vW2, vb2,
        idx_i, idx_j, idx_k, idx_kj, idx_ji, T);
    attn_out_kernel<<<(E * 32 + 255) / 256, 256>>>(idx_ji, T, E, (float*)d_out);
}

// round 4
// speedup vs baseline: 1.3439x; 1.2361x over previous
#include <cuda_runtime.h>
#include <math.h>

// ---------------------------------------------------------------------------
// BondUpdateLayer, round 4: 128-row tiles, occ-1, cp.async double-buffered
// weights, shuffle-based LayerNorm, FFMA2 GEMM cores.
//   K1a: per-edge distance gaussians
//   K1b: per-edge Q MLP (128-row tiles)
//   K2 : per-triplet kv assembly + hk MLP -> logits, hv MLP -> V (2 launches)
//   K3 : per-edge segment softmax (idx_ji sorted => contiguous segments)
// ---------------------------------------------------------------------------

#define EN    80000
#define TMAXN 640000

typedef unsigned long long ull;

__device__ float g_rfeat [EN * 20];
__device__ float g_q     [EN * 128];
__device__ float g_logits[(size_t)TMAXN * 16];
__device__ float g_v     [(size_t)TMAXN * 128];

__device__ __forceinline__ ull pack2(float v) {
    ull r;
    asm("mov.b64 %0, {%1, %1};" : "=l"(r) : "f"(v));
    return r;
}
__device__ __forceinline__ void fma2(ull& d, ull a, ull b) {
    asm("fma.rn.f32x2 %0, %1, %2, %0;" : "+l"(d) : "l"(a), "l"(b));
}
__device__ __forceinline__ float2 unpack2(ull v) {
    float lo, hi;
    asm("mov.b64 {%0, %1}, %2;" : "=f"(lo), "=f"(hi) : "l"(v));
    return make_float2(lo, hi);
}

// ---- cp.async weight chunk loader: 32 k-rows x 128 cols into Wb[buf] ----
__device__ __forceinline__ void load_chunk(const float* __restrict__ W, int kdim,
                                           int c, int buf, float* Wb, int tid)
{
    float* dst = Wb + buf * 4096;
    #pragma unroll
    for (int i = 0; i < 4; i++) {
        int v = tid + i * 256;            // 0..1023 float4 slots
        int krow = c * 32 + (v >> 5);
        float* d = dst + v * 4;
        if (krow < kdim) {
            unsigned sa = (unsigned)__cvta_generic_to_shared(d);
            const float* s = W + (size_t)krow * 128 + (v & 31) * 4;
            asm volatile("cp.async.cg.shared.global [%0], [%1], 16;" :: "r"(sa), "l"(s));
        } else {
            d[0] = 0.f; d[1] = 0.f; d[2] = 0.f; d[3] = 0.f;
        }
    }
    asm volatile("cp.async.commit_group;");
}

// ---- one 32-k GEMM chunk: acc[8 rows][4 col-pairs] += Xp @ Wp ----
__device__ __forceinline__ void gemm_chunk(const float* __restrict__ Xp, int xstride,
                                           const float* __restrict__ Wp, int tx,
                                           ull acc[8][4])
{
    const ulonglong2* Wq = (const ulonglong2*)Wp + tx * 2;
    #pragma unroll 4
    for (int kk = 0; kk < 32; ++kk) {
        ulonglong2 w0 = Wq[kk * 32];
        ulonglong2 w1 = Wq[kk * 32 + 1];
        #pragma unroll
        for (int r = 0; r < 8; r++) {
            ull ap = pack2(Xp[r * xstride + kk]);
            fma2(acc[r][0], ap, w0.x);
            fma2(acc[r][1], ap, w0.y);
            fma2(acc[r][2], ap, w1.x);
            fma2(acc[r][3], ap, w1.y);
        }
    }
}

// ---- 128-row MLP: Linear -> LayerNorm -> ReLU -> Linear ----
// Caller must have committed cp.async groups for W1 chunks 0 (buf0) and 1 (buf1).
__device__ __forceinline__ void mlp128(
    const float* __restrict__ Xs, int xstride, int n1, int kdim1,
    const float* __restrict__ W1, const float* __restrict__ b1,
    const float* __restrict__ gam, const float* __restrict__ bet,
    const float* __restrict__ W2, const float* __restrict__ b2,
    float* Hs, float* Wb, int tid, int tx, int ty, float out[8][8])
{
    ull a1p[8][4];
    #pragma unroll
    for (int r = 0; r < 8; r++)
        #pragma unroll
        for (int c = 0; c < 4; c++) a1p[r][c] = 0ULL;

    const float* Xp = Xs + (ty * 8) * xstride;

    // -------- GEMM1 --------
    for (int c = 0; c < n1; c++) {
        asm volatile("cp.async.wait_group 1;");
        __syncthreads();
        gemm_chunk(Xp + c * 32, xstride, Wb + (c & 1) * 4096, tx, a1p);
        __syncthreads();
        if (c + 2 < n1) load_chunk(W1, kdim1, c + 2, c & 1, Wb, tid);
        else            asm volatile("cp.async.commit_group;");
    }

    // prefetch W2 chunks 0,1 (overlaps LayerNorm below)
    load_chunk(W2, 128, 0, 0, Wb, tid);
    load_chunk(W2, 128, 1, 1, Wb, tid);

    // -------- bias + LayerNorm (shuffle over the 16 tx lanes) + ReLU --------
    float bb[8], gg[8], be[8];
    #pragma unroll
    for (int c = 0; c < 8; c++) {
        bb[c] = b1[tx * 8 + c]; gg[c] = gam[tx * 8 + c]; be[c] = bet[tx * 8 + c];
    }
    float a1[8][8];
    #pragma unroll
    for (int r = 0; r < 8; r++) {
        float s = 0.f, s2 = 0.f;
        #pragma unroll
        for (int cp = 0; cp < 4; cp++) {
            float2 t = unpack2(a1p[r][cp]);
            float x0 = t.x + bb[cp * 2];
            float x1 = t.y + bb[cp * 2 + 1];
            a1[r][cp * 2]     = x0;
            a1[r][cp * 2 + 1] = x1;
            s += x0 + x1; s2 += x0 * x0 + x1 * x1;
        }
        #pragma unroll
        for (int o = 1; o < 16; o <<= 1) {
            s  += __shfl_xor_sync(0xffffffffu, s,  o);
            s2 += __shfl_xor_sync(0xffffffffu, s2, o);
        }
        float mu  = s * (1.f / 128.f);
        float var = fmaxf(s2 * (1.f / 128.f) - mu * mu, 0.f);
        float rs  = rsqrtf(var + 1e-5f);
        int row = ty * 8 + r;
        #pragma unroll
        for (int c = 0; c < 8; c++) {
            float h = gg[c] * (a1[r][c] - mu) * rs + be[c];
            Hs[row * 132 + tx * 8 + c] = fmaxf(h, 0.f);
        }
    }

    // -------- GEMM2 --------
    ull a2p[8][4];
    #pragma unroll
    for (int r = 0; r < 8; r++)
        #pragma unroll
        for (int c = 0; c < 4; c++) a2p[r][c] = 0ULL;

    const float* Hp = Hs + (ty * 8) * 132;
    for (int c = 0; c < 4; c++) {
        asm volatile("cp.async.wait_group 1;");
        __syncthreads();
        gemm_chunk(Hp + c * 32, 132, Wb + (c & 1) * 4096, tx, a2p);
        __syncthreads();
        if (c + 2 < 4) load_chunk(W2, 128, c + 2, c & 1, Wb, tid);
        else           asm volatile("cp.async.commit_group;");
    }
    #pragma unroll
    for (int r = 0; r < 8; r++)
        #pragma unroll
        for (int cp = 0; cp < 4; cp++) {
            float2 t = unpack2(a2p[r][cp]);
            out[r][cp * 2]     = t.x + b2[tx * 8 + cp * 2];
            out[r][cp * 2 + 1] = t.y + b2[tx * 8 + cp * 2 + 1];
        }
}

// ---------------- K1a: edge gaussian features ----------------
__global__ void edge_feat_kernel(const float* __restrict__ pos,
                                 const int* __restrict__ brow,
                                 const int* __restrict__ bcol, int E)
{
    int e = blockIdx.x * blockDim.x + threadIdx.x;
    if (e >= E) return;
    int r = brow[e], c = bcol[e];
    float dx = pos[c*3+0] - pos[r*3+0];
    float dy = pos[c*3+1] - pos[r*3+1];
    float dz = pos[c*3+2] - pos[r*3+2];
    float d  = sqrtf(dx*dx + dy*dy + dz*dz);
    const float step  = 10.0f / 19.0f;
    const float coeff = -0.5f / (step * step);
    #pragma unroll
    for (int g = 0; g < 20; ++g) {
        float t = d - step * (float)g;
        g_rfeat[e*20 + g] = expf(coeff * t * t);
    }
}

// ---------------- K1b: Q MLP over edges (128-row tiles) ----------------
__global__ void __launch_bounds__(256, 1) q_mlp_kernel(const float* __restrict__ h_bond,
    const float* __restrict__ W1, const float* __restrict__ b1,
    const float* __restrict__ gam, const float* __restrict__ bet,
    const float* __restrict__ W2, const float* __restrict__ b2, int E)
{
    extern __shared__ float sm[];
    float* Xs = sm;                    // 128*132
    float* Hs = Xs + 128*132;          // 128*132
    float* Wb = Hs + 128*132;          // 2*4096
    int tid = threadIdx.x, tx = tid & 15, ty = tid >> 4;
    int e0 = blockIdx.x * 128;

    load_chunk(W1, 128, 0, 0, Wb, tid);
    load_chunk(W1, 128, 1, 1, Wb, tid);

    for (int v = tid; v < 128*32; v += 256) {
        int row = v >> 5, c4 = v & 31;
        float4 x = make_float4(0.f, 0.f, 0.f, 0.f);
        if (e0 + row < E) x = ((const float4*)h_bond)[(size_t)(e0 + row)*32 + c4];
        float* xr = Xs + row*132 + c4*4;
        xr[0] = x.x; xr[1] = x.y; xr[2] = x.z; xr[3] = x.w;
    }

    float out[8][8];
    mlp128(Xs, 132, 4, 128, W1, b1, gam, bet, W2, b2, Hs, Wb, tid, tx, ty, out);

    #pragma unroll
    for (int r = 0; r < 8; r++) {
        int e = e0 + ty*8 + r;
        if (e < E) {
            float4 o0 = make_float4(out[r][0], out[r][1], out[r][2], out[r][3]);
            float4 o1 = make_float4(out[r][4], out[r][5], out[r][6], out[r][7]);
            float4* qp = (float4*)(g_q + (size_t)e*128 + tx*8);
            qp[0] = o0; qp[1] = o1;
        }
    }
}

// ---------------- K2: triplet kv -> hk (logits), hv (V) ----------------
__global__ void __launch_bounds__(256, 1) triplet_kernel(
    const float* __restrict__ h_bond, const float* __restrict__ pos,
    const float* __restrict__ kW1, const float* __restrict__ kb1,
    const float* __restrict__ kg,  const float* __restrict__ kb,
    const float* __restrict__ kW2, const float* __restrict__ kb2,
    const float* __restrict__ vW1, const float* __restrict__ vb1,
    const float* __restrict__ vg,  const float* __restrict__ vb,
    const float* __restrict__ vW2, const float* __restrict__ vb2,
    const int* __restrict__ idx_i, const int* __restrict__ idx_j,
    const int* __restrict__ idx_k, const int* __restrict__ idx_kj,
    const int* __restrict__ idx_ji, int blk0, int T)
{
    extern __shared__ float sm[];
    const int XS = 196;                 // 192 data cols + 4 pad
    float* Xs  = sm;                    // 128*196
    float* Hs  = Xs + 128*XS;           // 128*132
    float* Wb  = Hs + 128*132;          // 2*4096
    int*   kjS = (int*)(Wb + 2*4096);   // 128
    int*   jiS = kjS + 128;             // 128

    int tid = threadIdx.x, tx = tid & 15, ty = tid >> 4;
    int t0 = (blockIdx.x + blk0) * 128;

    // prefetch hk W1 chunks 0,1 (overlaps assembly)
    load_chunk(kW1, 181, 0, 0, Wb, tid);
    load_chunk(kW1, 181, 1, 1, Wb, tid);

    // zero the kv tile
    for (int v = tid; v < 128*XS/4; v += 256)
        ((float4*)Xs)[v] = make_float4(0.f, 0.f, 0.f, 0.f);
    __syncthreads();

    // per-row indices + angular features (cols 168..180)
    if (tid < 128) {
        int t = t0 + tid;
        if (t < T) {
            int kj = idx_kj[t], ji = idx_ji[t];
            kjS[tid] = kj; jiS[tid] = ji;
            int ii = idx_i[t], jj = idx_j[t], kk = idx_k[t];
            float pix = pos[ii*3+0], piy = pos[ii*3+1], piz = pos[ii*3+2];
            float jx = pos[jj*3+0]-pix, jy = pos[jj*3+1]-piy, jz = pos[jj*3+2]-piz;
            float kx = pos[kk*3+0]-pix, ky = pos[kk*3+1]-piy, kz = pos[kk*3+2]-piz;
            float dt = jx*kx + jy*ky + jz*kz;
            float cx = jy*kz - jz*ky, cy = jz*kx - jx*kz, cz = jx*ky - jy*kx;
            float cr = sqrtf(cx*cx + cy*cy + cz*cz);
            float ang = atan2f(cr, dt);
            float* xr = Xs + tid*XS + 168;
            xr[0] = ang;
            const float fq[6] = {1.f, 2.f, 3.f, 1.f, 0.5f, 1.f/3.f};
            #pragma unroll
            for (int i = 0; i < 6; i++) {
                xr[1 + i] = sinf(ang * fq[i]);
                xr[7 + i] = cosf(ang * fq[i]);
            }
        } else {
            kjS[tid] = -1; jiS[tid] = -1;
        }
    }
    __syncthreads();

    // h_bond[idx_kj] gather -> cols 0..127
    for (int v = tid; v < 128*32; v += 256) {
        int row = v >> 5, c4 = v & 31;
        int kj = kjS[row];
        if (kj >= 0) {
            float4 hb = ((const float4*)h_bond)[(size_t)kj*32 + c4];
            float* xr = Xs + row*XS + c4*4;
            xr[0] = hb.x; xr[1] = hb.y; xr[2] = hb.z; xr[3] = hb.w;
        }
    }
    // rfeat gathers -> cols 128..147 (kj), 148..167 (ji)
    for (int v = tid; v < 128*20; v += 256) {
        int row = v / 20, g = v % 20;
        int kj = kjS[row];
        if (kj >= 0) {
            Xs[row*XS + 128 + g] = g_rfeat[kj*20 + g];
            Xs[row*XS + 148 + g] = g_rfeat[jiS[row]*20 + g];
        }
    }
    __syncthreads();

    float out[8][8];

    // -------- hk MLP -> logits --------
    mlp128(Xs, XS, 6, 181, kW1, kb1, kg, kb, kW2, kb2, Hs, Wb, tid, tx, ty, out);

    // prefetch hv W1 (overlaps logits epilogue)
    load_chunk(vW1, 181, 0, 0, Wb, tid);
    load_chunk(vW1, 181, 1, 1, Wb, tid);

    const float scale = 0.3535533905932738f;  // 1/sqrt(8)
    #pragma unroll
    for (int r = 0; r < 8; r++) {
        int row = ty*8 + r;
        int ji = jiS[row];
        if (ji >= 0) {
            const float4* qp = (const float4*)(g_q + (size_t)ji*128 + tx*8);
            float4 q0 = qp[0], q1 = qp[1];
            float lg = out[r][0]*q0.x + out[r][1]*q0.y + out[r][2]*q0.z + out[r][3]*q0.w
                     + out[r][4]*q1.x + out[r][5]*q1.y + out[r][6]*q1.z + out[r][7]*q1.w;
            g_logits[(size_t)(t0 + row)*16 + tx] = lg * scale;
        }
    }

    // -------- hv MLP -> V --------
    mlp128(Xs, XS, 6, 181, vW1, vb1, vg, vb, vW2, vb2, Hs, Wb, tid, tx, ty, out);
    #pragma unroll
    for (int r = 0; r < 8; r++) {
        int row = ty*8 + r;
        if (jiS[row] >= 0) {
            float4 o0 = make_float4(out[r][0], out[r][1], out[r][2], out[r][3]);
            float4 o1 = make_float4(out[r][4], out[r][5], out[r][6], out[r][7]);
            float4* vp = (float4*)(g_v + (size_t)(t0 + row)*128 + tx*8);
            vp[0] = o0; vp[1] = o1;
        }
    }
}

// ---------------- K3: per-edge segment softmax + weighted V sum ----------------
__global__ void attn_out_kernel(const int* __restrict__ idx_ji,
                                int T, int E, float* __restrict__ out)
{
    int warp = (blockIdx.x * blockDim.x + threadIdx.x) >> 5;
    int lane = threadIdx.x & 31;
    if (warp >= E) return;
    int e = warp;

    int lo = 0, hi = T;
    while (lo < hi) { int m = (lo + hi) >> 1; if (idx_ji[m] <  e)     lo = m + 1; else hi = m; }
    int s = lo;
    int hi2 = T;
    while (lo < hi2) { int m = (lo + hi2) >> 1; if (idx_ji[m] < e + 1) lo = m + 1; else hi2 = m; }
    int en = lo;

    int head = lane >> 1, half = lane & 1;

    float mx = -INFINITY;
    for (int t = s; t < en; t++) mx = fmaxf(mx, g_logits[(size_t)t*16 + head]);

    float den = 0.f;
    float ax = 0.f, ay = 0.f, az = 0.f, aw = 0.f;
    for (int t = s; t < en; t++) {
        float w = expf(g_logits[(size_t)t*16 + head] - mx);
        den += w;
        float4 v = *(const float4*)(g_v + (size_t)t*128 + head*8 + half*4);
        ax += w * v.x; ay += w * v.y; az += w * v.z; aw += w * v.w;
    }
    float inv = (en > s) ? (1.f / den) : 0.f;
    float4 o = make_float4(ax * inv, ay * inv, az * inv, aw * inv);
    *(float4*)(out + (size_t)e*128 + head*8 + half*4) = o;
}

// ---------------- launcher ----------------
extern "C" void kernel_launch(void* const* d_in, const int* in_sizes, int n_in,
                              void* d_out, int out_size)
{
    const float* h_bond = (const float*)d_in[1];
    const float* pos    = (const float*)d_in[2];
    const float* kW1 = (const float*)d_in[3];
    const float* kb1 = (const float*)d_in[4];
    const float* kg  = (const float*)d_in[5];
    const float* kb  = (const float*)d_in[6];
    const float* kW2 = (const float*)d_in[7];
    const float* kb2 = (const float*)d_in[8];
    const float* vW1 = (const float*)d_in[9];
    const float* vb1 = (const float*)d_in[10];
    const float* vg  = (const float*)d_in[11];
    const float* vb  = (const float*)d_in[12];
    const float* vW2 = (const float*)d_in[13];
    const float* vb2 = (const float*)d_in[14];
    const float* qW1 = (const float*)d_in[15];
    const float* qb1 = (const float*)d_in[16];
    const float* qg  = (const float*)d_in[17];
    const float* qb  = (const float*)d_in[18];
    const float* qW2 = (const float*)d_in[19];
    const float* qb2 = (const float*)d_in[20];
    const int* bond_row = (const int*)d_in[21];
    const int* bond_col = (const int*)d_in[22];
    const int* idx_i  = (const int*)d_in[23];
    const int* idx_j  = (const int*)d_in[24];
    const int* idx_k  = (const int*)d_in[25];
    const int* idx_kj = (const int*)d_in[26];
    const int* idx_ji = (const int*)d_in[27];
    int E = in_sizes[21];
    int T = in_sizes[23];

    const int SMEM_T = (128*196 + 128*132 + 2*4096 + 256) * 4;   // 201,728 B
    const int SMEM_Q = (128*132 + 128*132 + 2*4096) * 4;         // 167,936 B
    cudaFuncSetAttribute(q_mlp_kernel,   cudaFuncAttributeMaxDynamicSharedMemorySize, SMEM_Q);
    cudaFuncSetAttribute(triplet_kernel, cudaFuncAttributeMaxDynamicSharedMemorySize, SMEM_T);

    int nb  = (T + 127) / 128;
    int nbA = nb / 2; if (nbA < 1) nbA = 1;
    int nbB = nb - nbA;

    edge_feat_kernel<<<(E + 255) / 256, 256>>>(pos, bond_row, bond_col, E);
    q_mlp_kernel<<<(E + 127) / 128, 256, SMEM_Q>>>(h_bond, qW1, qb1, qg, qb, qW2, qb2, E);
    triplet_kernel<<<nbA, 256, SMEM_T>>>(
        h_bond, pos,
        kW1, kb1, kg, kb, kW2, kb2,
        vW1, vb1, vg, vb, vW2, vb2,
        idx_i, idx_j, idx_k, idx_kj, idx_ji, 0, T);
    if (nbB > 0)
        triplet_kernel<<<nbB, 256, SMEM_T>>>(
            h_bond, pos,
            kW1, kb1, kg, kb, kW2, kb2,
            vW1, vb1, vg, vb, vW2, vb2,
            idx_i, idx_j, idx_k, idx_kj, idx_ji, nbA, T);
    attn_out_kernel<<<(E * 32 + 255) / 256, 256>>>(idx_ji, T, E, (float*)d_out);
}

// round 5
// speedup vs baseline: 1.4917x; 1.1100x over previous
#include <cuda_runtime.h>
#include <math.h>

// ---------------------------------------------------------------------------
// BondUpdateLayer, round 5: float4-vectorized activation LDS in GEMM cores
// (crossbar was the binding constraint at fma=49%), minimal Xs zeroing.
// ---------------------------------------------------------------------------

#define EN    80000
#define TMAXN 640000

typedef unsigned long long ull;

__device__ float g_rfeat [EN * 20];
__device__ float g_q     [EN * 128];
__device__ float g_logits[(size_t)TMAXN * 16];
__device__ float g_v     [(size_t)TMAXN * 128];

__device__ __forceinline__ ull pack2(float v) {
    ull r;
    asm("mov.b64 %0, {%1, %1};" : "=l"(r) : "f"(v));
    return r;
}
__device__ __forceinline__ void fma2(ull& d, ull a, ull b) {
    asm("fma.rn.f32x2 %0, %1, %2, %0;" : "+l"(d) : "l"(a), "l"(b));
}
__device__ __forceinline__ float2 unpack2(ull v) {
    float lo, hi;
    asm("mov.b64 {%0, %1}, %2;" : "=f"(lo), "=f"(hi) : "l"(v));
    return make_float2(lo, hi);
}

// ---- cp.async weight chunk loader: 32 k-rows x 128 cols into Wb[buf] ----
__device__ __forceinline__ void load_chunk(const float* __restrict__ W, int kdim,
                                           int c, int buf, float* Wb, int tid)
{
    float* dst = Wb + buf * 4096;
    #pragma unroll
    for (int i = 0; i < 4; i++) {
        int v = tid + i * 256;            // 0..1023 float4 slots
        int krow = c * 32 + (v >> 5);
        float* d = dst + v * 4;
        if (krow < kdim) {
            unsigned sa = (unsigned)__cvta_generic_to_shared(d);
            const float* s = W + (size_t)krow * 128 + (v & 31) * 4;
            asm volatile("cp.async.cg.shared.global [%0], [%1], 16;" :: "r"(sa), "l"(s));
        } else {
            d[0] = 0.f; d[1] = 0.f; d[2] = 0.f; d[3] = 0.f;
        }
    }
    asm volatile("cp.async.commit_group;");
}

// ---- one 32-k GEMM chunk: acc[8 rows][4 col-pairs] += Xp @ Wp ----
// Activations loaded as float4 over k (4 kk per load) -> 4x fewer act LDS.
__device__ __forceinline__ void gemm_chunk(const float* __restrict__ Xp, int xstride,
                                           const float* __restrict__ Wp, int tx,
                                           ull acc[8][4])
{
    const ulonglong2* Wq = (const ulonglong2*)Wp + tx * 2;
    #pragma unroll
    for (int kq = 0; kq < 8; ++kq) {
        float4 av[8];
        #pragma unroll
        for (int r = 0; r < 8; r++)
            av[r] = *(const float4*)(Xp + r * xstride + kq * 4);
        #pragma unroll
        for (int k4 = 0; k4 < 4; ++k4) {
            int kk = kq * 4 + k4;
            ulonglong2 w0 = Wq[kk * 32];
            ulonglong2 w1 = Wq[kk * 32 + 1];
            #pragma unroll
            for (int r = 0; r < 8; r++) {
                float a = (k4 == 0) ? av[r].x : (k4 == 1) ? av[r].y
                        : (k4 == 2) ? av[r].z : av[r].w;
                ull ap = pack2(a);
                fma2(acc[r][0], ap, w0.x);
                fma2(acc[r][1], ap, w0.y);
                fma2(acc[r][2], ap, w1.x);
                fma2(acc[r][3], ap, w1.y);
            }
        }
    }
}

// ---- 128-row MLP: Linear -> LayerNorm -> ReLU -> Linear ----
// Caller must have committed cp.async groups for W1 chunks 0 (buf0) and 1 (buf1).
__device__ __forceinline__ void mlp128(
    const float* __restrict__ Xs, int xstride, int n1, int kdim1,
    const float* __restrict__ W1, const float* __restrict__ b1,
    const float* __restrict__ gam, const float* __restrict__ bet,
    const float* __restrict__ W2, const float* __restrict__ b2,
    float* Hs, float* Wb, int tid, int tx, int ty, float out[8][8])
{
    ull a1p[8][4];
    #pragma unroll
    for (int r = 0; r < 8; r++)
        #pragma unroll
        for (int c = 0; c < 4; c++) a1p[r][c] = 0ULL;

    const float* Xp = Xs + (ty * 8) * xstride;

    // -------- GEMM1 --------
    for (int c = 0; c < n1; c++) {
        asm volatile("cp.async.wait_group 1;");
        __syncthreads();
        gemm_chunk(Xp + c * 32, xstride, Wb + (c & 1) * 4096, tx, a1p);
        __syncthreads();
        if (c + 2 < n1) load_chunk(W1, kdim1, c + 2, c & 1, Wb, tid);
        else            asm volatile("cp.async.commit_group;");
    }

    // prefetch W2 chunks 0,1 (overlaps LayerNorm below)
    load_chunk(W2, 128, 0, 0, Wb, tid);
    load_chunk(W2, 128, 1, 1, Wb, tid);

    // -------- bias + LayerNorm (shuffle over the 16 tx lanes) + ReLU --------
    float bb[8], gg[8], be[8];
    #pragma unroll
    for (int c = 0; c < 8; c++) {
        bb[c] = b1[tx * 8 + c]; gg[c] = gam[tx * 8 + c]; be[c] = bet[tx * 8 + c];
    }
    float a1[8][8];
    #pragma unroll
    for (int r = 0; r < 8; r++) {
        float s = 0.f, s2 = 0.f;
        #pragma unroll
        for (int cp = 0; cp < 4; cp++) {
            float2 t = unpack2(a1p[r][cp]);
            float x0 = t.x + bb[cp * 2];
            float x1 = t.y + bb[cp * 2 + 1];
            a1[r][cp * 2]     = x0;
            a1[r][cp * 2 + 1] = x1;
            s += x0 + x1; s2 += x0 * x0 + x1 * x1;
        }
        #pragma unroll
        for (int o = 1; o < 16; o <<= 1) {
            s  += __shfl_xor_sync(0xffffffffu, s,  o);
            s2 += __shfl_xor_sync(0xffffffffu, s2, o);
        }
        float mu  = s * (1.f / 128.f);
        float var = fmaxf(s2 * (1.f / 128.f) - mu * mu, 0.f);
        float rs  = rsqrtf(var + 1e-5f);
        int row = ty * 8 + r;
        #pragma unroll
        for (int c = 0; c < 8; c++) {
            float h = gg[c] * (a1[r][c] - mu) * rs + be[c];
            Hs[row * 132 + tx * 8 + c] = fmaxf(h, 0.f);
        }
    }

    // -------- GEMM2 --------
    ull a2p[8][4];
    #pragma unroll
    for (int r = 0; r < 8; r++)
        #pragma unroll
        for (int c = 0; c < 4; c++) a2p[r][c] = 0ULL;

    const float* Hp = Hs + (ty * 8) * 132;
    for (int c = 0; c < 4; c++) {
        asm volatile("cp.async.wait_group 1;");
        __syncthreads();
        gemm_chunk(Hp + c * 32, 132, Wb + (c & 1) * 4096, tx, a2p);
        __syncthreads();
        if (c + 2 < 4) load_chunk(W2, 128, c + 2, c & 1, Wb, tid);
        else           asm volatile("cp.async.commit_group;");
    }
    #pragma unroll
    for (int r = 0; r < 8; r++)
        #pragma unroll
        for (int cp = 0; cp < 4; cp++) {
            float2 t = unpack2(a2p[r][cp]);
            out[r][cp * 2]     = t.x + b2[tx * 8 + cp * 2];
            out[r][cp * 2 + 1] = t.y + b2[tx * 8 + cp * 2 + 1];
        }
}

// ---------------- K1a: edge gaussian features ----------------
__global__ void edge_feat_kernel(const float* __restrict__ pos,
                                 const int* __restrict__ brow,
                                 const int* __restrict__ bcol, int E)
{
    int e = blockIdx.x * blockDim.x + threadIdx.x;
    if (e >= E) return;
    int r = brow[e], c = bcol[e];
    float dx = pos[c*3+0] - pos[r*3+0];
    float dy = pos[c*3+1] - pos[r*3+1];
    float dz = pos[c*3+2] - pos[r*3+2];
    float d  = sqrtf(dx*dx + dy*dy + dz*dz);
    const float step  = 10.0f / 19.0f;
    const float coeff = -0.5f / (step * step);
    #pragma unroll
    for (int g = 0; g < 20; ++g) {
        float t = d - step * (float)g;
        g_rfeat[e*20 + g] = expf(coeff * t * t);
    }
}

// ---------------- K1b: Q MLP over edges (128-row tiles) ----------------
__global__ void __launch_bounds__(256, 1) q_mlp_kernel(const float* __restrict__ h_bond,
    const float* __restrict__ W1, const float* __restrict__ b1,
    const float* __restrict__ gam, const float* __restrict__ bet,
    const float* __restrict__ W2, const float* __restrict__ b2, int E)
{
    extern __shared__ float sm[];
    float* Xs = sm;                    // 128*132
    float* Hs = Xs + 128*132;          // 128*132
    float* Wb = Hs + 128*132;          // 2*4096
    int tid = threadIdx.x, tx = tid & 15, ty = tid >> 4;
    int e0 = blockIdx.x * 128;

    load_chunk(W1, 128, 0, 0, Wb, tid);
    load_chunk(W1, 128, 1, 1, Wb, tid);

    for (int v = tid; v < 128*32; v += 256) {
        int row = v >> 5, c4 = v & 31;
        float4 x = make_float4(0.f, 0.f, 0.f, 0.f);
        if (e0 + row < E) x = ((const float4*)h_bond)[(size_t)(e0 + row)*32 + c4];
        float* xr = Xs + row*132 + c4*4;
        xr[0] = x.x; xr[1] = x.y; xr[2] = x.z; xr[3] = x.w;
    }

    float out[8][8];
    mlp128(Xs, 132, 4, 128, W1, b1, gam, bet, W2, b2, Hs, Wb, tid, tx, ty, out);

    #pragma unroll
    for (int r = 0; r < 8; r++) {
        int e = e0 + ty*8 + r;
        if (e < E) {
            float4 o0 = make_float4(out[r][0], out[r][1], out[r][2], out[r][3]);
            float4 o1 = make_float4(out[r][4], out[r][5], out[r][6], out[r][7]);
            float4* qp = (float4*)(g_q + (size_t)e*128 + tx*8);
            qp[0] = o0; qp[1] = o1;
        }
    }
}

// ---------------- K2: triplet kv -> hk (logits), hv (V) ----------------
__global__ void __launch_bounds__(256, 1) triplet_kernel(
    const float* __restrict__ h_bond, const float* __restrict__ pos,
    const float* __restrict__ kW1, const float* __restrict__ kb1,
    const float* __restrict__ kg,  const float* __restrict__ kb,
    const float* __restrict__ kW2, const float* __restrict__ kb2,
    const float* __restrict__ vW1, const float* __restrict__ vb1,
    const float* __restrict__ vg,  const float* __restrict__ vb,
    const float* __restrict__ vW2, const float* __restrict__ vb2,
    const int* __restrict__ idx_i, const int* __restrict__ idx_j,
    const int* __restrict__ idx_k, const int* __restrict__ idx_kj,
    const int* __restrict__ idx_ji, int blk0, int T)
{
    extern __shared__ float sm[];
    const int XS = 196;                 // 192 data cols + 4 pad
    float* Xs  = sm;                    // 128*196
    float* Hs  = Xs + 128*XS;           // 128*132
    float* Wb  = Hs + 128*132;          // 2*4096
    int*   kjS = (int*)(Wb + 2*4096);   // 128
    int*   jiS = kjS + 128;             // 128

    int tid = threadIdx.x, tx = tid & 15, ty = tid >> 4;
    int t0 = (blockIdx.x + blk0) * 128;

    // prefetch hk W1 chunks 0,1 (overlaps assembly)
    load_chunk(kW1, 181, 0, 0, Wb, tid);
    load_chunk(kW1, 181, 1, 1, Wb, tid);

    // zero only the tail cols 176..195 (weight rows >= kdim are zero-filled,
    // so garbage beyond col 180 would only matter as NaN*0 -> keep it zeroed)
    for (int v = tid; v < 128*5; v += 256) {
        int row = v / 5, c4 = v % 5;
        ((float4*)(Xs + row*XS + 176))[c4] = make_float4(0.f, 0.f, 0.f, 0.f);
    }
    __syncthreads();

    // per-row indices + angular features (cols 168..180)
    if (tid < 128) {
        int t = t0 + tid;
        if (t < T) {
            int kj = idx_kj[t], ji = idx_ji[t];
            kjS[tid] = kj; jiS[tid] = ji;
            int ii = idx_i[t], jj = idx_j[t], kk = idx_k[t];
            float pix = pos[ii*3+0], piy = pos[ii*3+1], piz = pos[ii*3+2];
            float jx = pos[jj*3+0]-pix, jy = pos[jj*3+1]-piy, jz = pos[jj*3+2]-piz;
            float kx = pos[kk*3+0]-pix, ky = pos[kk*3+1]-piy, kz = pos[kk*3+2]-piz;
            float dt = jx*kx + jy*ky + jz*kz;
            float cx = jy*kz - jz*ky, cy = jz*kx - jx*kz, cz = jx*ky - jy*kx;
            float cr = sqrtf(cx*cx + cy*cy + cz*cz);
            float ang = atan2f(cr, dt);
            float* xr = Xs + tid*XS + 168;
            xr[0] = ang;
            const float fq[6] = {1.f, 2.f, 3.f, 1.f, 0.5f, 1.f/3.f};
            #pragma unroll
            for (int i = 0; i < 6; i++) {
                xr[1 + i] = sinf(ang * fq[i]);
                xr[7 + i] = cosf(ang * fq[i]);
            }
        } else {
            kjS[tid] = -1; jiS[tid] = -1;
            // keep invalid rows finite across the k range GEMM reads
            float* xr = Xs + tid*XS;
            #pragma unroll
            for (int c4 = 0; c4 < 44; c4++)
                ((float4*)xr)[c4] = make_float4(0.f, 0.f, 0.f, 0.f);
        }
    }
    __syncthreads();

    // h_bond[idx_kj] gather -> cols 0..127
    for (int v = tid; v < 128*32; v += 256) {
        int row = v >> 5, c4 = v & 31;
        int kj = kjS[row];
        if (kj >= 0) {
            float4 hb = ((const float4*)h_bond)[(size_t)kj*32 + c4];
            float* xr = Xs + row*XS + c4*4;
            xr[0] = hb.x; xr[1] = hb.y; xr[2] = hb.z; xr[3] = hb.w;
        }
    }
    // rfeat gathers -> cols 128..147 (kj), 148..167 (ji)
    for (int v = tid; v < 128*20; v += 256) {
        int row = v / 20, g = v % 20;
        int kj = kjS[row];
        if (kj >= 0) {
            Xs[row*XS + 128 + g] = g_rfeat[kj*20 + g];
            Xs[row*XS + 148 + g] = g_rfeat[jiS[row]*20 + g];
        }
    }
    __syncthreads();

    float out[8][8];

    // -------- hk MLP -> logits --------
    mlp128(Xs, XS, 6, 181, kW1, kb1, kg, kb, kW2, kb2, Hs, Wb, tid, tx, ty, out);

    // prefetch hv W1 (overlaps logits epilogue)
    load_chunk(vW1, 181, 0, 0, Wb, tid);
    load_chunk(vW1, 181, 1, 1, Wb, tid);

    const float scale = 0.3535533905932738f;  // 1/sqrt(8)
    #pragma unroll
    for (int r = 0; r < 8; r++) {
        int row = ty*8 + r;
        int ji = jiS[row];
        if (ji >= 0) {
            const float4* qp = (const float4*)(g_q + (size_t)ji*128 + tx*8);
            float4 q0 = qp[0], q1 = qp[1];
            float lg = out[r][0]*q0.x + out[r][1]*q0.y + out[r][2]*q0.z + out[r][3]*q0.w
                     + out[r][4]*q1.x + out[r][5]*q1.y + out[r][6]*q1.z + out[r][7]*q1.w;
            g_logits[(size_t)(t0 + row)*16 + tx] = lg * scale;
        }
    }

    // -------- hv MLP -> V --------
    mlp128(Xs, XS, 6, 181, vW1, vb1, vg, vb, vW2, vb2, Hs, Wb, tid, tx, ty, out);
    #pragma unroll
    for (int r = 0; r < 8; r++) {
        int row = ty*8 + r;
        if (jiS[row] >= 0) {
            float4 o0 = make_float4(out[r][0], out[r][1], out[r][2], out[r][3]);
            float4 o1 = make_float4(out[r][4], out[r][5], out[r][6], out[r][7]);
            float4* vp = (float4*)(g_v + (size_t)(t0 + row)*128 + tx*8);
            vp[0] = o0; vp[1] = o1;
        }
    }
}

// ---------------- K3: per-edge segment softmax + weighted V sum ----------------
__global__ void attn_out_kernel(const int* __restrict__ idx_ji,
                                int T, int E, float* __restrict__ out)
{
    int warp = (blockIdx.x * blockDim.x + threadIdx.x) >> 5;
    int lane = threadIdx.x & 31;
    if (warp >= E) return;
    int e = warp;

    int lo = 0, hi = T;
    while (lo < hi) { int m = (lo + hi) >> 1; if (idx_ji[m] <  e)     lo = m + 1; else hi = m; }
    int s = lo;
    int hi2 = T;
    while (lo < hi2) { int m = (lo + hi2) >> 1; if (idx_ji[m] < e + 1) lo = m + 1; else hi2 = m; }
    int en = lo;

    int head = lane >> 1, half = lane & 1;

    float mx = -INFINITY;
    for (int t = s; t < en; t++) mx = fmaxf(mx, g_logits[(size_t)t*16 + head]);

    float den = 0.f;
    float ax = 0.f, ay = 0.f, az = 0.f, aw = 0.f;
    for (int t = s; t < en; t++) {
        float w = expf(g_logits[(size_t)t*16 + head] - mx);
        den += w;
        float4 v = *(const float4*)(g_v + (size_t)t*128 + head*8 + half*4);
        ax += w * v.x; ay += w * v.y; az += w * v.z; aw += w * v.w;
    }
    float inv = (en > s) ? (1.f / den) : 0.f;
    float4 o = make_float4(ax * inv, ay * inv, az * inv, aw * inv);
    *(float4*)(out + (size_t)e*128 + head*8 + half*4) = o;
}

// ---------------- launcher ----------------
extern "C" void kernel_launch(void* const* d_in, const int* in_sizes, int n_in,
                              void* d_out, int out_size)
{
    const float* h_bond = (const float*)d_in[1];
    const float* pos    = (const float*)d_in[2];
    const float* kW1 = (const float*)d_in[3];
    const float* kb1 = (const float*)d_in[4];
    const float* kg  = (const float*)d_in[5];
    const float* kb  = (const float*)d_in[6];
    const float* kW2 = (const float*)d_in[7];
    const float* kb2 = (const float*)d_in[8];
    const float* vW1 = (const float*)d_in[9];
    const float* vb1 = (const float*)d_in[10];
    const float* vg  = (const float*)d_in[11];
    const float* vb  = (const float*)d_in[12];
    const float* vW2 = (const float*)d_in[13];
    const float* vb2 = (const float*)d_in[14];
    const float* qW1 = (const float*)d_in[15];
    const float* qb1 = (const float*)d_in[16];
    const float* qg  = (const float*)d_in[17];
    const float* qb  = (const float*)d_in[18];
    const float* qW2 = (const float*)d_in[19];
    const float* qb2 = (const float*)d_in[20];
    const int* bond_row = (const int*)d_in[21];
    const int* bond_col = (const int*)d_in[22];
    const int* idx_i  = (const int*)d_in[23];
    const int* idx_j  = (const int*)d_in[24];
    const int* idx_k  = (const int*)d_in[25];
    const int* idx_kj = (const int*)d_in[26];
    const int* idx_ji = (const int*)d_in[27];
    int E = in_sizes[21];
    int T = in_sizes[23];

    const int SMEM_T = (128*196 + 128*132 + 2*4096 + 256) * 4;   // 201,728 B
    const int SMEM_Q = (128*132 + 128*132 + 2*4096) * 4;         // 167,936 B
    cudaFuncSetAttribute(q_mlp_kernel,   cudaFuncAttributeMaxDynamicSharedMemorySize, SMEM_Q);
    cudaFuncSetAttribute(triplet_kernel, cudaFuncAttributeMaxDynamicSharedMemorySize, SMEM_T);

    int nb  = (T + 127) / 128;
    int nbA = nb / 2; if (nbA < 1) nbA = 1;
    int nbB = nb - nbA;

    edge_feat_kernel<<<(E + 255) / 256, 256>>>(pos, bond_row, bond_col, E);
    q_mlp_kernel<<<(E + 127) / 128, 256, SMEM_Q>>>(h_bond, qW1, qb1, qg, qb, qW2, qb2, E);
    triplet_kernel<<<nbA, 256, SMEM_T>>>(
        h_bond, pos,
        kW1, kb1, kg, kb, kW2, kb2,
        vW1, vb1, vg, vb, vW2, vb2,
        idx_i, idx_j, idx_k, idx_kj, idx_ji, 0, T);
    if (nbB > 0)
        triplet_kernel<<<nbB, 256, SMEM_T>>>(
            h_bond, pos,
            kW1, kb1, kg, kb, kW2, kb2,
            vW1, vb1, vg, vb, vW2, vb2,
            idx_i, idx_j, idx_k, idx_kj, idx_ji, nbA, T);
    attn_out_kernel<<<(E * 32 + 255) / 256, 256>>>(idx_ji, T, E, (float*)d_out);
}

// round 6
// speedup vs baseline: 1.5671x; 1.0506x over previous
#include <cuda_runtime.h>
#include <math.h>

// ---------------------------------------------------------------------------
// BondUpdateLayer, round 6: column-specialized warps (warp = 16 output cols,
// lane = 4 rows at stride 32). Weight LDS become same-address broadcasts,
// activation LDS become conflict-free (stride = 4 mod 32 banks). FFMA2 cores,
// cp.async double-buffered weights, smem-partial LayerNorm.
// ---------------------------------------------------------------------------

#define EN    80000
#define TMAXN 640000

typedef unsigned long long ull;

__device__ float g_rfeat [EN * 20];
__device__ float g_q     [EN * 128];
__device__ float g_logits[(size_t)TMAXN * 16];
__device__ float g_v     [(size_t)TMAXN * 128];

__device__ __forceinline__ ull pack2(float v) {
    ull r;
    asm("mov.b64 %0, {%1, %1};" : "=l"(r) : "f"(v));
    return r;
}
__device__ __forceinline__ void fma2(ull& d, ull a, ull b) {
    asm("fma.rn.f32x2 %0, %1, %2, %0;" : "+l"(d) : "l"(a), "l"(b));
}
__device__ __forceinline__ float2 unpack2(ull v) {
    float lo, hi;
    asm("mov.b64 {%0, %1}, %2;" : "=f"(lo), "=f"(hi) : "l"(v));
    return make_float2(lo, hi);
}

// ---- cp.async weight chunk loader: 32 k-rows x 128 cols into Wb[buf] ----
__device__ __forceinline__ void load_chunk(const float* __restrict__ W, int kdim,
                                           int c, int buf, float* Wb, int tid)
{
    float* dst = Wb + buf * 4096;
    #pragma unroll
    for (int i = 0; i < 4; i++) {
        int v = tid + i * 256;            // 0..1023 float4 slots
        int krow = c * 32 + (v >> 5);
        float* d = dst + v * 4;
        if (krow < kdim) {
            unsigned sa = (unsigned)__cvta_generic_to_shared(d);
            const float* s = W + (size_t)krow * 128 + (v & 31) * 4;
            asm volatile("cp.async.cg.shared.global [%0], [%1], 16;" :: "r"(sa), "l"(s));
        } else {
            d[0] = 0.f; d[1] = 0.f; d[2] = 0.f; d[3] = 0.f;
        }
    }
    asm volatile("cp.async.commit_group;");
}

// ---- one 32-k GEMM chunk, column-warp layout ----
// Xl: this lane's row-0 pointer (already offset by chunk k), rows at rr*32*xstride.
// Wp: weight chunk base; this warp reads cols [w16, w16+16).
// acc[4 rows][8 col-pairs]
__device__ __forceinline__ void gemm_chunk_cw(const float* __restrict__ Xl, int xstride,
                                              const float* __restrict__ Wp, int w16,
                                              ull acc[4][8])
{
    #pragma unroll
    for (int kq = 0; kq < 8; ++kq) {
        float4 av[4];
        #pragma unroll
        for (int rr = 0; rr < 4; rr++)
            av[rr] = *(const float4*)(Xl + rr * 32 * xstride + kq * 4);
        #pragma unroll
        for (int k4 = 0; k4 < 4; ++k4) {
            const ulonglong2* wp = (const ulonglong2*)(Wp + (kq * 4 + k4) * 128 + w16);
            ulonglong2 wA = wp[0];
            ulonglong2 wB = wp[1];
            ulonglong2 wC = wp[2];
            ulonglong2 wD = wp[3];
            #pragma unroll
            for (int rr = 0; rr < 4; rr++) {
                float a = (k4 == 0) ? av[rr].x : (k4 == 1) ? av[rr].y
                        : (k4 == 2) ? av[rr].z : av[rr].w;
                ull ap = pack2(a);
                fma2(acc[rr][0], ap, wA.x);
                fma2(acc[rr][1], ap, wA.y);
                fma2(acc[rr][2], ap, wB.x);
                fma2(acc[rr][3], ap, wB.y);
                fma2(acc[rr][4], ap, wC.x);
                fma2(acc[rr][5], ap, wC.y);
                fma2(acc[rr][6], ap, wD.x);
                fma2(acc[rr][7], ap, wD.y);
            }
        }
    }
}

// ---- 128-row MLP, column-warp layout ----
// Thread (w = tid>>5, l = tid&31): rows {l, 32+l, 64+l, 96+l}, cols [16w, 16w+16).
// red: 2*1152 floats (stride-9 padded partials), mus/rss: 128 each.
// Caller must have committed cp.async groups for W1 chunks 0 (buf0) and 1 (buf1).
__device__ __forceinline__ void mlp128cw(
    const float* __restrict__ Xs, int xstride, int n1, int kdim1,
    const float* __restrict__ b1,
    const float* __restrict__ gam, const float* __restrict__ bet,
    const float* __restrict__ W1,
    const float* __restrict__ W2, const float* __restrict__ b2,
    float* Hs, float* Wb, float* red, float* mus, float* rss,
    int tid, int l, int w, float out[4][16])
{
    const int w16 = w * 16;
    ull a1p[4][8];
    #pragma unroll
    for (int r = 0; r < 4; r++)
        #pragma unroll
        for (int c = 0; c < 8; c++) a1p[r][c] = 0ULL;

    const float* Xl = Xs + l * xstride;

    // -------- GEMM1 --------
    for (int c = 0; c < n1; c++) {
        asm volatile("cp.async.wait_group 1;");
        __syncthreads();
        gemm_chunk_cw(Xl + c * 32, xstride, Wb + (c & 1) * 4096, w16, a1p);
        __syncthreads();
        if (c + 2 < n1) load_chunk(W1, kdim1, c + 2, c & 1, Wb, tid);
        else            asm volatile("cp.async.commit_group;");
    }

    // prefetch W2 chunks 0,1 (overlaps LayerNorm below)
    load_chunk(W2, 128, 0, 0, Wb, tid);
    load_chunk(W2, 128, 1, 1, Wb, tid);

    // -------- bias + partial sums --------
    float a1[4][16];
    #pragma unroll
    for (int r = 0; r < 4; r++) {
        float s = 0.f, s2 = 0.f;
        #pragma unroll
        for (int cp = 0; cp < 8; cp++) {
            float2 t = unpack2(a1p[r][cp]);
            float x0 = t.x + b1[w16 + cp * 2];
            float x1 = t.y + b1[w16 + cp * 2 + 1];
            a1[r][cp * 2]     = x0;
            a1[r][cp * 2 + 1] = x1;
            s += x0 + x1; s2 += x0 * x0 + x1 * x1;
        }
        int row = r * 32 + l;
        red[row * 9 + w]        = s;
        red[1152 + row * 9 + w] = s2;
    }
    __syncthreads();
    if (tid < 128) {
        float s = 0.f, s2 = 0.f;
        #pragma unroll
        for (int i = 0; i < 8; i++) { s += red[tid * 9 + i]; s2 += red[1152 + tid * 9 + i]; }
        float mu  = s * (1.f / 128.f);
        float var = fmaxf(s2 * (1.f / 128.f) - mu * mu, 0.f);
        mus[tid] = mu;
        rss[tid] = rsqrtf(var + 1e-5f);
    }
    __syncthreads();

    // -------- LayerNorm + ReLU -> Hs --------
    #pragma unroll
    for (int r = 0; r < 4; r++) {
        int row = r * 32 + l;
        float mu = mus[row], rs = rss[row];
        float4 hv[4];
        #pragma unroll
        for (int c = 0; c < 16; c++) {
            float h = gam[w16 + c] * (a1[r][c] - mu) * rs + bet[w16 + c];
            ((float*)hv)[c] = fmaxf(h, 0.f);
        }
        float4* hp = (float4*)(Hs + row * 132 + w16);
        hp[0] = hv[0]; hp[1] = hv[1]; hp[2] = hv[2]; hp[3] = hv[3];
    }

    // -------- GEMM2 --------
    ull a2p[4][8];
    #pragma unroll
    for (int r = 0; r < 4; r++)
        #pragma unroll
        for (int c = 0; c < 8; c++) a2p[r][c] = 0ULL;

    const float* Hl = Hs + l * 132;
    for (int c = 0; c < 4; c++) {
        asm volatile("cp.async.wait_group 1;");
        __syncthreads();
        gemm_chunk_cw(Hl + c * 32, 132, Wb + (c & 1) * 4096, w16, a2p);
        __syncthreads();
        if (c + 2 < 4) load_chunk(W2, 128, c + 2, c & 1, Wb, tid);
        else           asm volatile("cp.async.commit_group;");
    }
    #pragma unroll
    for (int r = 0; r < 4; r++)
        #pragma unroll
        for (int cp = 0; cp < 8; cp++) {
            float2 t = unpack2(a2p[r][cp]);
            out[r][cp * 2]     = t.x + b2[w16 + cp * 2];
            out[r][cp * 2 + 1] = t.y + b2[w16 + cp * 2 + 1];
        }
}

// ---------------- K1a: edge gaussian features ----------------
__global__ void edge_feat_kernel(const float* __restrict__ pos,
                                 const int* __restrict__ brow,
                                 const int* __restrict__ bcol, int E)
{
    int e = blockIdx.x * blockDim.x + threadIdx.x;
    if (e >= E) return;
    int r = brow[e], c = bcol[e];
    float dx = pos[c*3+0] - pos[r*3+0];
    float dy = pos[c*3+1] - pos[r*3+1];
    float dz = pos[c*3+2] - pos[r*3+2];
    float d  = sqrtf(dx*dx + dy*dy + dz*dz);
    const float step  = 10.0f / 19.0f;
    const float coeff = -0.5f / (step * step);
    #pragma unroll
    for (int g = 0; g < 20; ++g) {
        float t = d - step * (float)g;
        g_rfeat[e*20 + g] = expf(coeff * t * t);
    }
}

// ---------------- K1b: Q MLP over edges ----------------
__global__ void __launch_bounds__(256, 1) q_mlp_kernel(const float* __restrict__ h_bond,
    const float* __restrict__ W1, const float* __restrict__ b1,
    const float* __restrict__ gam, const float* __restrict__ bet,
    const float* __restrict__ W2, const float* __restrict__ b2, int E)
{
    extern __shared__ float sm[];
    float* Xs  = sm;                   // 128*132
    float* Hs  = Xs + 128*132;         // 128*132
    float* Wb  = Hs + 128*132;         // 2*4096
    float* red = Wb + 2*4096;          // 2*1152
    float* mus = red + 2*1152;         // 128
    float* rss = mus + 128;            // 128
    int tid = threadIdx.x, l = tid & 31, w = tid >> 5;
    int e0 = blockIdx.x * 128;

    load_chunk(W1, 128, 0, 0, Wb, tid);
    load_chunk(W1, 128, 1, 1, Wb, tid);

    for (int v = tid; v < 128*32; v += 256) {
        int row = v >> 5, c4 = v & 31;
        float4 x = make_float4(0.f, 0.f, 0.f, 0.f);
        if (e0 + row < E) x = ((const float4*)h_bond)[(size_t)(e0 + row)*32 + c4];
        float* xr = Xs + row*132 + c4*4;
        xr[0] = x.x; xr[1] = x.y; xr[2] = x.z; xr[3] = x.w;
    }

    float out[4][16];
    mlp128cw(Xs, 132, 4, 128, b1, gam, bet, W1, W2, b2,
             Hs, Wb, red, mus, rss, tid, l, w, out);

    #pragma unroll
    for (int r = 0; r < 4; r++) {
        int row = r * 32 + l;
        int e = e0 + row;
        if (e < E) {
            float4* qp = (float4*)(g_q + (size_t)e*128 + w*16);
            qp[0] = *(float4*)&out[r][0];
            qp[1] = *(float4*)&out[r][4];
            qp[2] = *(float4*)&out[r][8];
            qp[3] = *(float4*)&out[r][12];
        }
    }
}

// ---------------- K2: triplet kv -> hk (logits), hv (V) ----------------
__global__ void __launch_bounds__(256, 1) triplet_kernel(
    const float* __restrict__ h_bond, const float* __restrict__ pos,
    const float* __restrict__ kW1, const float* __restrict__ kb1,
    const float* __restrict__ kg,  const float* __restrict__ kb,
    const float* __restrict__ kW2, const float* __restrict__ kb2,
    const float* __restrict__ vW1, const float* __restrict__ vb1,
    const float* __restrict__ vg,  const float* __restrict__ vb,
    const float* __restrict__ vW2, const float* __restrict__ vb2,
    const int* __restrict__ idx_i, const int* __restrict__ idx_j,
    const int* __restrict__ idx_k, const int* __restrict__ idx_kj,
    const int* __restrict__ idx_ji, int blk0, int T)
{
    extern __shared__ float sm[];
    const int XS = 196;                 // 192 data cols + 4 pad (== 4 mod 32)
    float* Xs  = sm;                    // 128*196
    float* Hs  = Xs + 128*XS;           // 128*132
    float* Wb  = Hs + 128*132;          // 2*4096
    float* red = Wb + 2*4096;           // 2*1152
    float* mus = red + 2*1152;          // 128
    float* rss = mus + 128;             // 128
    int*   kjS = (int*)(rss + 128);     // 128
    int*   jiS = kjS + 128;             // 128

    int tid = threadIdx.x, l = tid & 31, w = tid >> 5;
    int t0 = (blockIdx.x + blk0) * 128;

    // prefetch hk W1 chunks 0,1 (overlaps assembly)
    load_chunk(kW1, 181, 0, 0, Wb, tid);
    load_chunk(kW1, 181, 1, 1, Wb, tid);

    // zero tail cols 176..195 (weight rows >= kdim are zero-filled; garbage
    // beyond col 180 must stay finite)
    for (int v = tid; v < 128*5; v += 256) {
        int row = v / 5, c4 = v % 5;
        ((float4*)(Xs + row*XS + 176))[c4] = make_float4(0.f, 0.f, 0.f, 0.f);
    }
    __syncthreads();

    // per-row indices + angular features (cols 168..180)
    if (tid < 128) {
        int t = t0 + tid;
        if (t < T) {
            int kj = idx_kj[t], ji = idx_ji[t];
            kjS[tid] = kj; jiS[tid] = ji;
            int ii = idx_i[t], jj = idx_j[t], kk = idx_k[t];
            float pix = pos[ii*3+0], piy = pos[ii*3+1], piz = pos[ii*3+2];
            float jx = pos[jj*3+0]-pix, jy = pos[jj*3+1]-piy, jz = pos[jj*3+2]-piz;
            float kx = pos[kk*3+0]-pix, ky = pos[kk*3+1]-piy, kz = pos[kk*3+2]-piz;
            float dt = jx*kx + jy*ky + jz*kz;
            float cx = jy*kz - jz*ky, cy = jz*kx - jx*kz, cz = jx*ky - jy*kx;
            float cr = sqrtf(cx*cx + cy*cy + cz*cz);
            float ang = atan2f(cr, dt);
            float* xr = Xs + tid*XS + 168;
            xr[0] = ang;
            const float fq[6] = {1.f, 2.f, 3.f, 1.f, 0.5f, 1.f/3.f};
            #pragma unroll
            for (int i = 0; i < 6; i++) {
                xr[1 + i] = sinf(ang * fq[i]);
                xr[7 + i] = cosf(ang * fq[i]);
            }
        } else {
            kjS[tid] = -1; jiS[tid] = -1;
            // keep invalid rows finite across the k range GEMM reads
            float* xr = Xs + tid*XS;
            #pragma unroll
            for (int c4 = 0; c4 < 44; c4++)
                ((float4*)xr)[c4] = make_float4(0.f, 0.f, 0.f, 0.f);
        }
    }
    __syncthreads();

    // h_bond[idx_kj] gather -> cols 0..127
    for (int v = tid; v < 128*32; v += 256) {
        int row = v >> 5, c4 = v & 31;
        int kj = kjS[row];
        if (kj >= 0) {
            float4 hb = ((const float4*)h_bond)[(size_t)kj*32 + c4];
            float* xr = Xs + row*XS + c4*4;
            xr[0] = hb.x; xr[1] = hb.y; xr[2] = hb.z; xr[3] = hb.w;
        }
    }
    // rfeat gathers -> cols 128..147 (kj), 148..167 (ji)
    for (int v = tid; v < 128*20; v += 256) {
        int row = v / 20, g = v % 20;
        int kj = kjS[row];
        if (kj >= 0) {
            Xs[row*XS + 128 + g] = g_rfeat[kj*20 + g];
            Xs[row*XS + 148 + g] = g_rfeat[jiS[row]*20 + g];
        }
    }
    __syncthreads();

    float out[4][16];

    // -------- hk MLP -> logits --------
    mlp128cw(Xs, XS, 6, 181, kb1, kg, kb, kW1, kW2, kb2,
             Hs, Wb, red, mus, rss, tid, l, w, out);

    // prefetch hv W1 (overlaps logits epilogue)
    load_chunk(vW1, 181, 0, 0, Wb, tid);
    load_chunk(vW1, 181, 1, 1, Wb, tid);

    const float scale = 0.3535533905932738f;  // 1/sqrt(8)
    #pragma unroll
    for (int r = 0; r < 4; r++) {
        int row = r * 32 + l;
        int ji = jiS[row];
        if (ji >= 0) {
            const float4* qp = (const float4*)(g_q + (size_t)ji*128 + w*16);
            float4 q0 = qp[0], q1 = qp[1], q2 = qp[2], q3 = qp[3];
            float lg0 = out[r][0]*q0.x + out[r][1]*q0.y + out[r][2]*q0.z + out[r][3]*q0.w
                      + out[r][4]*q1.x + out[r][5]*q1.y + out[r][6]*q1.z + out[r][7]*q1.w;
            float lg1 = out[r][8]*q2.x + out[r][9]*q2.y + out[r][10]*q2.z + out[r][11]*q2.w
                      + out[r][12]*q3.x + out[r][13]*q3.y + out[r][14]*q3.z + out[r][15]*q3.w;
            g_logits[(size_t)(t0 + row)*16 + 2*w]     = lg0 * scale;
            g_logits[(size_t)(t0 + row)*16 + 2*w + 1] = lg1 * scale;
        }
    }

    // -------- hv MLP -> V --------
    mlp128cw(Xs, XS, 6, 181, vb1, vg, vb, vW1, vW2, vb2,
             Hs, Wb, red, mus, rss, tid, l, w, out);
    #pragma unroll
    for (int r = 0; r < 4; r++) {
        int row = r * 32 + l;
        if (jiS[row] >= 0) {
            float4* vp = (float4*)(g_v + (size_t)(t0 + row)*128 + w*16);
            vp[0] = *(float4*)&out[r][0];
            vp[1] = *(float4*)&out[r][4];
            vp[2] = *(float4*)&out[r][8];
            vp[3] = *(float4*)&out[r][12];
        }
    }
}

// ---------------- K3: per-edge segment softmax + weighted V sum ----------------
__global__ void attn_out_kernel(const int* __restrict__ idx_ji,
                                int T, int E, float* __restrict__ out)
{
    int warp = (blockIdx.x * blockDim.x + threadIdx.x) >> 5;
    int lane = threadIdx.x & 31;
    if (warp >= E) return;
    int e = warp;

    int lo = 0, hi = T;
    while (lo < hi) { int m = (lo + hi) >> 1; if (idx_ji[m] <  e)     lo = m + 1; else hi = m; }
    int s = lo;
    int hi2 = T;
    while (lo < hi2) { int m = (lo + hi2) >> 1; if (idx_ji[m] < e + 1) lo = m + 1; else hi2 = m; }
    int en = lo;

    int head = lane >> 1, half = lane & 1;

    float mx = -INFINITY;
    for (int t = s; t < en; t++) mx = fmaxf(mx, g_logits[(size_t)t*16 + head]);

    float den = 0.f;
    float ax = 0.f, ay = 0.f, az = 0.f, aw = 0.f;
    for (int t = s; t < en; t++) {
        float w = expf(g_logits[(size_t)t*16 + head] - mx);
        den += w;
        float4 v = *(const float4*)(g_v + (size_t)t*128 + head*8 + half*4);
        ax += w * v.x; ay += w * v.y; az += w * v.z; aw += w * v.w;
    }
    float inv = (en > s) ? (1.f / den) : 0.f;
    float4 o = make_float4(ax * inv, ay * inv, az * inv, aw * inv);
    *(float4*)(out + (size_t)e*128 + head*8 + half*4) = o;
}

// ---------------- launcher ----------------
extern "C" void kernel_launch(void* const* d_in, const int* in_sizes, int n_in,
                              void* d_out, int out_size)
{
    const float* h_bond = (const float*)d_in[1];
    const float* pos    = (const float*)d_in[2];
    const float* kW1 = (const float*)d_in[3];
    const float* kb1 = (const float*)d_in[4];
    const float* kg  = (const float*)d_in[5];
    const float* kb  = (const float*)d_in[6];
    const float* kW2 = (const float*)d_in[7];
    const float* kb2 = (const float*)d_in[8];
    const float* vW1 = (const float*)d_in[9];
    const float* vb1 = (const float*)d_in[10];
    const float* vg  = (const float*)d_in[11];
    const float* vb  = (const float*)d_in[12];
    const float* vW2 = (const float*)d_in[13];
    const float* vb2 = (const float*)d_in[14];
    const float* qW1 = (const float*)d_in[15];
    const float* qb1 = (const float*)d_in[16];
    const float* qg  = (const float*)d_in[17];
    const float* qb  = (const float*)d_in[18];
    const float* qW2 = (const float*)d_in[19];
    const float* qb2 = (const float*)d_in[20];
    const int* bond_row = (const int*)d_in[21];
    const int* bond_col = (const int*)d_in[22];
    const int* idx_i  = (const int*)d_in[23];
    const int* idx_j  = (const int*)d_in[24];
    const int* idx_k  = (const int*)d_in[25];
    const int* idx_kj = (const int*)d_in[26];
    const int* idx_ji = (const int*)d_in[27];
    int E = in_sizes[21];
    int T = in_sizes[23];

    // smem: Xs + Hs + Wb + red(2*1152) + mus/rss(256) + idx(256 ints)
    const int SMEM_T = (128*196 + 128*132 + 2*4096 + 2*1152 + 256 + 256) * 4; // 211,968 B
    const int SMEM_Q = (128*132 + 128*132 + 2*4096 + 2*1152 + 256) * 4;       // 178,176 B
    cudaFuncSetAttribute(q_mlp_kernel,   cudaFuncAttributeMaxDynamicSharedMemorySize, SMEM_Q);
    cudaFuncSetAttribute(triplet_kernel, cudaFuncAttributeMaxDynamicSharedMemorySize, SMEM_T);

    int nb  = (T + 127) / 128;
    int nbA = nb / 2; if (nbA < 1) nbA = 1;
    int nbB = nb - nbA;

    edge_feat_kernel<<<(E + 255) / 256, 256>>>(pos, bond_row, bond_col, E);
    q_mlp_kernel<<<(E + 127) / 128, 256, SMEM_Q>>>(h_bond, qW1, qb1, qg, qb, qW2, qb2, E);
    triplet_kernel<<<nbA, 256, SMEM_T>>>(
        h_bond, pos,
        kW1, kb1, kg, kb, kW2, kb2,
        vW1, vb1, vg, vb, vW2, vb2,
        idx_i, idx_j, idx_k, idx_kj, idx_ji, 0, T);
    if (nbB > 0)
        triplet_kernel<<<nbB, 256, SMEM_T>>>(
            h_bond, pos,
            kW1, kb1, kg, kb, kW2, kb2,
            vW1, vb1, vg, vb, vW2, vb2,
            idx_i, idx_j, idx_k, idx_kj, idx_ji, nbA, T);
    attn_out_kernel<<<(E * 32 + 255) / 256, 256>>>(idx_ji, T, E, (float*)d_out);
}

// round 7
// speedup vs baseline: 1.5936x; 1.0169x over previous
#include <cuda_runtime.h>
#include <math.h>

// ---------------------------------------------------------------------------
// BondUpdateLayer, round 7: merged hk/hv GEMM1 (shared activation reads),
// 3-buffer single-sync cp.async weight rings, Hs aliased onto Xs.
// Column-warp FFMA2 GEMM cores as in round 6.
// ---------------------------------------------------------------------------

#define EN    80000
#define TMAXN 640000

typedef unsigned long long ull;

__device__ float g_rfeat [EN * 20];
__device__ float g_q     [EN * 128];
__device__ float g_logits[(size_t)TMAXN * 16];
__device__ float g_v     [(size_t)TMAXN * 128];

__device__ __forceinline__ ull pack2(float v) {
    ull r;
    asm("mov.b64 %0, {%1, %1};" : "=l"(r) : "f"(v));
    return r;
}
__device__ __forceinline__ void fma2(ull& d, ull a, ull b) {
    asm("fma.rn.f32x2 %0, %1, %2, %0;" : "+l"(d) : "l"(a), "l"(b));
}
__device__ __forceinline__ float2 unpack2(ull v) {
    float lo, hi;
    asm("mov.b64 {%0, %1}, %2;" : "=f"(lo), "=f"(hi) : "l"(v));
    return make_float2(lo, hi);
}

#define CP_COMMIT() asm volatile("cp.async.commit_group;")
#define CP_WAIT2()  asm volatile("cp.async.wait_group 2;")

// ---- cp.async weight chunk loader (no commit): 32 k-rows x 128 cols ----
__device__ __forceinline__ void load_chunk_nc(const float* __restrict__ W, int kdim,
                                              int c, float* dst, int tid)
{
    #pragma unroll
    for (int i = 0; i < 4; i++) {
        int v = tid + i * 256;            // 0..1023 float4 slots
        int krow = c * 32 + (v >> 5);
        float* d = dst + v * 4;
        if (krow < kdim) {
            unsigned sa = (unsigned)__cvta_generic_to_shared(d);
            const float* s = W + (size_t)krow * 128 + (v & 31) * 4;
            asm volatile("cp.async.cg.shared.global [%0], [%1], 16;" :: "r"(sa), "l"(s));
        } else {
            d[0] = 0.f; d[1] = 0.f; d[2] = 0.f; d[3] = 0.f;
        }
    }
}
// ---- with commit (legacy helper for q_mlp) ----
__device__ __forceinline__ void load_chunk(const float* __restrict__ W, int kdim,
                                           int c, int buf, float* Wb, int tid)
{
    load_chunk_nc(W, kdim, c, Wb + buf * 4096, tid);
    CP_COMMIT();
}

// ---- one 32-k GEMM chunk, column-warp layout, single weight ----
__device__ __forceinline__ void gemm_chunk_cw(const float* __restrict__ Xl, int xstride,
                                              const float* __restrict__ Wp, int w16,
                                              ull acc[4][8])
{
    #pragma unroll
    for (int kq = 0; kq < 8; ++kq) {
        float4 act[4];
        #pragma unroll
        for (int rr = 0; rr < 4; rr++)
            act[rr] = *(const float4*)(Xl + rr * 32 * xstride + kq * 4);
        #pragma unroll
        for (int k4 = 0; k4 < 4; ++k4) {
            const ulonglong2* wp = (const ulonglong2*)(Wp + (kq * 4 + k4) * 128 + w16);
            ulonglong2 wA = wp[0], wB = wp[1], wC = wp[2], wD = wp[3];
            #pragma unroll
            for (int rr = 0; rr < 4; rr++) {
                float a = (k4 == 0) ? act[rr].x : (k4 == 1) ? act[rr].y
                        : (k4 == 2) ? act[rr].z : act[rr].w;
                ull ap = pack2(a);
                fma2(acc[rr][0], ap, wA.x);
                fma2(acc[rr][1], ap, wA.y);
                fma2(acc[rr][2], ap, wB.x);
                fma2(acc[rr][3], ap, wB.y);
                fma2(acc[rr][4], ap, wC.x);
                fma2(acc[rr][5], ap, wC.y);
                fma2(acc[rr][6], ap, wD.x);
                fma2(acc[rr][7], ap, wD.y);
            }
        }
    }
}

// ---- merged chunk: update k-accums and v-accums from the same activations ----
__device__ __forceinline__ void gemm_chunk_cw2(const float* __restrict__ Xl, int xstride,
                                               const float* __restrict__ Kp,
                                               const float* __restrict__ Vp, int w16,
                                               ull ak[4][8], ull av_[4][8])
{
    #pragma unroll
    for (int kq = 0; kq < 8; ++kq) {
        float4 act[4];
        #pragma unroll
        for (int rr = 0; rr < 4; rr++)
            act[rr] = *(const float4*)(Xl + rr * 32 * xstride + kq * 4);
        #pragma unroll
        for (int k4 = 0; k4 < 4; ++k4) {
            int kk = kq * 4 + k4;
            ull ap[4];
            #pragma unroll
            for (int rr = 0; rr < 4; rr++) {
                float a = (k4 == 0) ? act[rr].x : (k4 == 1) ? act[rr].y
                        : (k4 == 2) ? act[rr].z : act[rr].w;
                ap[rr] = pack2(a);
            }
            {
                const ulonglong2* kp = (const ulonglong2*)(Kp + kk * 128 + w16);
                ulonglong2 wA = kp[0], wB = kp[1], wC = kp[2], wD = kp[3];
                #pragma unroll
                for (int rr = 0; rr < 4; rr++) {
                    fma2(ak[rr][0], ap[rr], wA.x);
                    fma2(ak[rr][1], ap[rr], wA.y);
                    fma2(ak[rr][2], ap[rr], wB.x);
                    fma2(ak[rr][3], ap[rr], wB.y);
                    fma2(ak[rr][4], ap[rr], wC.x);
                    fma2(ak[rr][5], ap[rr], wC.y);
                    fma2(ak[rr][6], ap[rr], wD.x);
                    fma2(ak[rr][7], ap[rr], wD.y);
                }
            }
            {
                const ulonglong2* vp = (const ulonglong2*)(Vp + kk * 128 + w16);
                ulonglong2 wA = vp[0], wB = vp[1], wC = vp[2], wD = vp[3];
                #pragma unroll
                for (int rr = 0; rr < 4; rr++) {
                    fma2(av_[rr][0], ap[rr], wA.x);
                    fma2(av_[rr][1], ap[rr], wA.y);
                    fma2(av_[rr][2], ap[rr], wB.x);
                    fma2(av_[rr][3], ap[rr], wB.y);
                    fma2(av_[rr][4], ap[rr], wC.x);
                    fma2(av_[rr][5], ap[rr], wC.y);
                    fma2(av_[rr][6], ap[rr], wD.x);
                    fma2(av_[rr][7], ap[rr], wD.y);
                }
            }
        }
    }
}

// ---- bias + LayerNorm + ReLU: acc -> Hs (stride 132). 2 internal syncs. ----
__device__ __forceinline__ void ln_relu(ull acc[4][8],
    const float* __restrict__ b1, const float* __restrict__ gam,
    const float* __restrict__ bet,
    float* Hs, float* red, float* mus, float* rss,
    int tid, int l, int w)
{
    const int w16 = w * 16;
    float a1[4][16];
    #pragma unroll
    for (int r = 0; r < 4; r++) {
        float s = 0.f, s2 = 0.f;
        #pragma unroll
        for (int cp = 0; cp < 8; cp++) {
            float2 t = unpack2(acc[r][cp]);
            float x0 = t.x + b1[w16 + cp * 2];
            float x1 = t.y + b1[w16 + cp * 2 + 1];
            a1[r][cp * 2]     = x0;
            a1[r][cp * 2 + 1] = x1;
            s += x0 + x1; s2 += x0 * x0 + x1 * x1;
        }
        int row = r * 32 + l;
        red[row * 9 + w]        = s;
        red[1152 + row * 9 + w] = s2;
    }
    __syncthreads();
    if (tid < 128) {
        float s = 0.f, s2 = 0.f;
        #pragma unroll
        for (int i = 0; i < 8; i++) { s += red[tid * 9 + i]; s2 += red[1152 + tid * 9 + i]; }
        float mu  = s * (1.f / 128.f);
        float var = fmaxf(s2 * (1.f / 128.f) - mu * mu, 0.f);
        mus[tid] = mu;
        rss[tid] = rsqrtf(var + 1e-5f);
    }
    __syncthreads();
    #pragma unroll
    for (int r = 0; r < 4; r++) {
        int row = r * 32 + l;
        float mu = mus[row], rs = rss[row];
        float4 hv[4];
        #pragma unroll
        for (int c = 0; c < 16; c++) {
            float h = gam[w16 + c] * (a1[r][c] - mu) * rs + bet[w16 + c];
            ((float*)hv)[c] = fmaxf(h, 0.f);
        }
        float4* hp = (float4*)(Hs + row * 132 + w16);
        hp[0] = hv[0]; hp[1] = hv[1]; hp[2] = hv[2]; hp[3] = hv[3];
    }
}

// ---------------- K1a: edge gaussian features ----------------
__global__ void edge_feat_kernel(const float* __restrict__ pos,
                                 const int* __restrict__ brow,
                                 const int* __restrict__ bcol, int E)
{
    int e = blockIdx.x * blockDim.x + threadIdx.x;
    if (e >= E) return;
    int r = brow[e], c = bcol[e];
    float dx = pos[c*3+0] - pos[r*3+0];
    float dy = pos[c*3+1] - pos[r*3+1];
    float dz = pos[c*3+2] - pos[r*3+2];
    float d  = sqrtf(dx*dx + dy*dy + dz*dz);
    const float step  = 10.0f / 19.0f;
    const float coeff = -0.5f / (step * step);
    #pragma unroll
    for (int g = 0; g < 20; ++g) {
        float t = d - step * (float)g;
        g_rfeat[e*20 + g] = expf(coeff * t * t);
    }
}

// ---------------- K1b: Q MLP over edges (round-6 structure, 2-buffer) -------
__device__ __forceinline__ void mlp128cw(
    const float* __restrict__ Xs, int xstride, int n1, int kdim1,
    const float* __restrict__ b1,
    const float* __restrict__ gam, const float* __restrict__ bet,
    const float* __restrict__ W1,
    const float* __restrict__ W2, const float* __restrict__ b2,
    float* Hs, float* Wb, float* red, float* mus, float* rss,
    int tid, int l, int w, float out[4][16])
{
    const int w16 = w * 16;
    ull a1p[4][8];
    #pragma unroll
    for (int r = 0; r < 4; r++)
        #pragma unroll
        for (int c = 0; c < 8; c++) a1p[r][c] = 0ULL;

    const float* Xl = Xs + l * xstride;

    for (int c = 0; c < n1; c++) {
        asm volatile("cp.async.wait_group 1;");
        __syncthreads();
        gemm_chunk_cw(Xl + c * 32, xstride, Wb + (c & 1) * 4096, w16, a1p);
        __syncthreads();
        if (c + 2 < n1) load_chunk(W1, kdim1, c + 2, c & 1, Wb, tid);
        else            CP_COMMIT();
    }
    load_chunk(W2, 128, 0, 0, Wb, tid);
    load_chunk(W2, 128, 1, 1, Wb, tid);

    ln_relu(a1p, b1, gam, bet, Hs, red, mus, rss, tid, l, w);

    ull a2p[4][8];
    #pragma unroll
    for (int r = 0; r < 4; r++)
        #pragma unroll
        for (int c = 0; c < 8; c++) a2p[r][c] = 0ULL;

    const float* Hl = Hs + l * 132;
    for (int c = 0; c < 4; c++) {
        asm volatile("cp.async.wait_group 1;");
        __syncthreads();
        gemm_chunk_cw(Hl + c * 32, 132, Wb + (c & 1) * 4096, w16, a2p);
        __syncthreads();
        if (c + 2 < 4) load_chunk(W2, 128, c + 2, c & 1, Wb, tid);
        else           CP_COMMIT();
    }
    #pragma unroll
    for (int r = 0; r < 4; r++)
        #pragma unroll
        for (int cp = 0; cp < 8; cp++) {
            float2 t = unpack2(a2p[r][cp]);
            out[r][cp * 2]     = t.x + b2[w16 + cp * 2];
            out[r][cp * 2 + 1] = t.y + b2[w16 + cp * 2 + 1];
        }
}

__global__ void __launch_bounds__(256, 1) q_mlp_kernel(const float* __restrict__ h_bond,
    const float* __restrict__ W1, const float* __restrict__ b1,
    const float* __restrict__ gam, const float* __restrict__ bet,
    const float* __restrict__ W2, const float* __restrict__ b2, int E)
{
    extern __shared__ float sm[];
    float* Xs  = sm;                   // 128*132
    float* Hs  = Xs + 128*132;         // 128*132
    float* Wb  = Hs + 128*132;         // 2*4096
    float* red = Wb + 2*4096;          // 2*1152
    float* mus = red + 2*1152;         // 128
    float* rss = mus + 128;            // 128
    int tid = threadIdx.x, l = tid & 31, w = tid >> 5;
    int e0 = blockIdx.x * 128;

    load_chunk(W1, 128, 0, 0, Wb, tid);
    load_chunk(W1, 128, 1, 1, Wb, tid);

    for (int v = tid; v < 128*32; v += 256) {
        int row = v >> 5, c4 = v & 31;
        float4 x = make_float4(0.f, 0.f, 0.f, 0.f);
        if (e0 + row < E) x = ((const float4*)h_bond)[(size_t)(e0 + row)*32 + c4];
        float* xr = Xs + row*132 + c4*4;
        xr[0] = x.x; xr[1] = x.y; xr[2] = x.z; xr[3] = x.w;
    }

    float out[4][16];
    mlp128cw(Xs, 132, 4, 128, b1, gam, bet, W1, W2, b2,
             Hs, Wb, red, mus, rss, tid, l, w, out);

    #pragma unroll
    for (int r = 0; r < 4; r++) {
        int row = r * 32 + l;
        int e = e0 + row;
        if (e < E) {
            float4* qp = (float4*)(g_q + (size_t)e*128 + w*16);
            qp[0] = *(float4*)&out[r][0];
            qp[1] = *(float4*)&out[r][4];
            qp[2] = *(float4*)&out[r][8];
            qp[3] = *(float4*)&out[r][12];
        }
    }
}

// ---------------- K2: triplet kv -> hk (logits), hv (V) ----------------
__global__ void __launch_bounds__(256, 1) triplet_kernel(
    const float* __restrict__ h_bond, const float* __restrict__ pos,
    const float* __restrict__ kW1, const float* __restrict__ kb1,
    const float* __restrict__ kg,  const float* __restrict__ kb,
    const float* __restrict__ kW2, const float* __restrict__ kb2,
    const float* __restrict__ vW1, const float* __restrict__ vb1,
    const float* __restrict__ vg,  const float* __restrict__ vb,
    const float* __restrict__ vW2, const float* __restrict__ vb2,
    const int* __restrict__ idx_i, const int* __restrict__ idx_j,
    const int* __restrict__ idx_k, const int* __restrict__ idx_kj,
    const int* __restrict__ idx_ji, int blk0, int T)
{
    extern __shared__ float sm[];
    const int XS = 196;                 // 192 data cols + 4 pad (== 4 mod 32)
    float* Xs  = sm;                    // 128*196 ; Hs aliases this after GEMM1
    float* KB  = Xs + 128*XS;           // 3*4096
    float* VB  = KB + 3*4096;           // 3*4096
    float* red = VB + 3*4096;           // 2*1152
    float* mus = red + 2*1152;          // 128
    float* rss = mus + 128;             // 128
    int*   kjS = (int*)(rss + 128);     // 128
    int*   jiS = kjS + 128;             // 128
    float* Hs  = Xs;                    // alias (stride 132, fits in Xs region)

    int tid = threadIdx.x, l = tid & 31, w = tid >> 5;
    const int w16 = w * 16;
    int t0 = (blockIdx.x + blk0) * 128;

    // preload merged-GEMM1 weight pairs: chunks 0,1 (one group per chunk pair)
    load_chunk_nc(kW1, 181, 0, KB + 0,    tid);
    load_chunk_nc(vW1, 181, 0, VB + 0,    tid);
    CP_COMMIT();
    load_chunk_nc(kW1, 181, 1, KB + 4096, tid);
    load_chunk_nc(vW1, 181, 1, VB + 4096, tid);
    CP_COMMIT();

    // zero tail cols 176..195
    for (int v = tid; v < 128*5; v += 256) {
        int row = v / 5, c4 = v % 5;
        ((float4*)(Xs + row*XS + 176))[c4] = make_float4(0.f, 0.f, 0.f, 0.f);
    }
    __syncthreads();

    // per-row indices + angular features (cols 168..180)
    if (tid < 128) {
        int t = t0 + tid;
        if (t < T) {
            int kj = idx_kj[t], ji = idx_ji[t];
            kjS[tid] = kj; jiS[tid] = ji;
            int ii = idx_i[t], jj = idx_j[t], kk = idx_k[t];
            float pix = pos[ii*3+0], piy = pos[ii*3+1], piz = pos[ii*3+2];
            float jx = pos[jj*3+0]-pix, jy = pos[jj*3+1]-piy, jz = pos[jj*3+2]-piz;
            float kx = pos[kk*3+0]-pix, ky = pos[kk*3+1]-piy, kz = pos[kk*3+2]-piz;
            float dt = jx*kx + jy*ky + jz*kz;
            float cx = jy*kz - jz*ky, cy = jz*kx - jx*kz, cz = jx*ky - jy*kx;
            float cr = sqrtf(cx*cx + cy*cy + cz*cz);
            float ang = atan2f(cr, dt);
            float* xr = Xs + tid*XS + 168;
            xr[0] = ang;
            const float fq[6] = {1.f, 2.f, 3.f, 1.f, 0.5f, 1.f/3.f};
            #pragma unroll
            for (int i = 0; i < 6; i++) {
                xr[1 + i] = sinf(ang * fq[i]);
                xr[7 + i] = cosf(ang * fq[i]);
            }
        } else {
            kjS[tid] = -1; jiS[tid] = -1;
            float* xr = Xs + tid*XS;
            #pragma unroll
            for (int c4 = 0; c4 < 44; c4++)
                ((float4*)xr)[c4] = make_float4(0.f, 0.f, 0.f, 0.f);
        }
    }
    __syncthreads();

    // h_bond[idx_kj] gather -> cols 0..127
    for (int v = tid; v < 128*32; v += 256) {
        int row = v >> 5, c4 = v & 31;
        int kj = kjS[row];
        if (kj >= 0) {
            float4 hb = ((const float4*)h_bond)[(size_t)kj*32 + c4];
            float* xr = Xs + row*XS + c4*4;
            xr[0] = hb.x; xr[1] = hb.y; xr[2] = hb.z; xr[3] = hb.w;
        }
    }
    // rfeat gathers -> cols 128..147 (kj), 148..167 (ji)
    for (int v = tid; v < 128*20; v += 256) {
        int row = v / 20, g = v % 20;
        int kj = kjS[row];
        if (kj >= 0) {
            Xs[row*XS + 128 + g] = g_rfeat[kj*20 + g];
            Xs[row*XS + 148 + g] = g_rfeat[jiS[row]*20 + g];
        }
    }

    // -------- merged GEMM1: 6 chunks, 3 buffers, 1 sync/chunk --------
    ull acck[4][8], accv[4][8];
    #pragma unroll
    for (int r = 0; r < 4; r++)
        #pragma unroll
        for (int c = 0; c < 8; c++) { acck[r][c] = 0ULL; accv[r][c] = 0ULL; }

    const float* Xl = Xs + l * XS;
    for (int c = 0; c < 6; c++) {
        __syncthreads();                       // chunk c-1 consumers done; assembly done (c=0)
        if (c + 2 < 6) {
            int b = (c + 2) % 3;
            load_chunk_nc(kW1, 181, c + 2, KB + b * 4096, tid);
            load_chunk_nc(vW1, 181, c + 2, VB + b * 4096, tid);
        }
        CP_COMMIT();
        CP_WAIT2();                            // chunk c landed (for all groups older than last 2)
        gemm_chunk_cw2(Xl + c * 32, XS, KB + (c % 3) * 4096, VB + (c % 3) * 4096,
                       w16, acck, accv);
    }

    // prefetch kW2 chunks 0,1 (KB0/KB1 free: last read chunk 3; synced since)
    load_chunk_nc(kW2, 128, 0, KB + 0,    tid); CP_COMMIT();
    load_chunk_nc(kW2, 128, 1, KB + 4096, tid); CP_COMMIT();

    // -------- LN-k -> Hs (aliased on Xs; safe: first ln sync retires all Xs readers)
    ln_relu(acck, kb1, kg, kb, Hs, red, mus, rss, tid, l, w);

    // -------- GEMM2-k --------
    #pragma unroll
    for (int r = 0; r < 4; r++)
        #pragma unroll
        for (int c = 0; c < 8; c++) acck[r][c] = 0ULL;
    const float* Hl = Hs + l * 132;
    for (int c = 0; c < 4; c++) {
        __syncthreads();
        if (c + 2 < 4) load_chunk_nc(kW2, 128, c + 2, KB + ((c + 2) % 3) * 4096, tid);
        CP_COMMIT();
        CP_WAIT2();
        gemm_chunk_cw(Hl + c * 32, 132, KB + (c % 3) * 4096, w16, acck);
    }

    // prefetch vW2 chunks 0,1 (VB free since GEMM1)
    load_chunk_nc(vW2, 128, 0, VB + 0,    tid); CP_COMMIT();
    load_chunk_nc(vW2, 128, 1, VB + 4096, tid); CP_COMMIT();

    // -------- logits epilogue --------
    const float scale = 0.3535533905932738f;  // 1/sqrt(8)
    #pragma unroll
    for (int r = 0; r < 4; r++) {
        int row = r * 32 + l;
        int ji = jiS[row];
        if (ji >= 0) {
            float outk[16];
            #pragma unroll
            for (int cp = 0; cp < 8; cp++) {
                float2 t = unpack2(acck[r][cp]);
                outk[cp * 2]     = t.x + kb2[w16 + cp * 2];
                outk[cp * 2 + 1] = t.y + kb2[w16 + cp * 2 + 1];
            }
            const float4* qp = (const float4*)(g_q + (size_t)ji*128 + w16);
            float4 q0 = qp[0], q1 = qp[1], q2 = qp[2], q3 = qp[3];
            float lg0 = outk[0]*q0.x + outk[1]*q0.y + outk[2]*q0.z + outk[3]*q0.w
                      + outk[4]*q1.x + outk[5]*q1.y + outk[6]*q1.z + outk[7]*q1.w;
            float lg1 = outk[8]*q2.x + outk[9]*q2.y + outk[10]*q2.z + outk[11]*q2.w
                      + outk[12]*q3.x + outk[13]*q3.y + outk[14]*q3.z + outk[15]*q3.w;
            g_logits[(size_t)(t0 + row)*16 + 2*w]     = lg0 * scale;
            g_logits[(size_t)(t0 + row)*16 + 2*w + 1] = lg1 * scale;
        }
    }

    // -------- LN-v -> Hs (sync first: GEMM2-k readers of Hs must retire) --------
    __syncthreads();
    ln_relu(accv, vb1, vg, vb, Hs, red, mus, rss, tid, l, w);

    // -------- GEMM2-v --------
    #pragma unroll
    for (int r = 0; r < 4; r++)
        #pragma unroll
        for (int c = 0; c < 8; c++) accv[r][c] = 0ULL;
    for (int c = 0; c < 4; c++) {
        __syncthreads();
        if (c + 2 < 4) load_chunk_nc(vW2, 128, c + 2, VB + ((c + 2) % 3) * 4096, tid);
        CP_COMMIT();
        CP_WAIT2();
        gemm_chunk_cw(Hl + c * 32, 132, VB + (c % 3) * 4096, w16, accv);
    }

    #pragma unroll
    for (int r = 0; r < 4; r++) {
        int row = r * 32 + l;
        if (jiS[row] >= 0) {
            float outv[16];
            #pragma unroll
            for (int cp = 0; cp < 8; cp++) {
                float2 t = unpack2(accv[r][cp]);
                outv[cp * 2]     = t.x + vb2[w16 + cp * 2];
                outv[cp * 2 + 1] = t.y + vb2[w16 + cp * 2 + 1];
            }
            float4* vp = (float4*)(g_v + (size_t)(t0 + row)*128 + w16);
            vp[0] = *(float4*)&outv[0];
            vp[1] = *(float4*)&outv[4];
            vp[2] = *(float4*)&outv[8];
            vp[3] = *(float4*)&outv[12];
        }
    }
}

// ---------------- K3: per-edge segment softmax + weighted V sum ----------------
__global__ void attn_out_kernel(const int* __restrict__ idx_ji,
                                int T, int E, float* __restrict__ out)
{
    int warp = (blockIdx.x * blockDim.x + threadIdx.x) >> 5;
    int lane = threadIdx.x & 31;
    if (warp >= E) return;
    int e = warp;

    int lo = 0, hi = T;
    while (lo < hi) { int m = (lo + hi) >> 1; if (idx_ji[m] <  e)     lo = m + 1; else hi = m; }
    int s = lo;
    int hi2 = T;
    while (lo < hi2) { int m = (lo + hi2) >> 1; if (idx_ji[m] < e + 1) lo = m + 1; else hi2 = m; }
    int en = lo;

    int head = lane >> 1, half = lane & 1;

    float mx = -INFINITY;
    for (int t = s; t < en; t++) mx = fmaxf(mx, g_logits[(size_t)t*16 + head]);

    float den = 0.f;
    float ax = 0.f, ay = 0.f, az = 0.f, aw = 0.f;
    for (int t = s; t < en; t++) {
        float w = expf(g_logits[(size_t)t*16 + head] - mx);
        den += w;
        float4 v = *(const float4*)(g_v + (size_t)t*128 + head*8 + half*4);
        ax += w * v.x; ay += w * v.y; az += w * v.z; aw += w * v.w;
    }
    float inv = (en > s) ? (1.f / den) : 0.f;
    float4 o = make_float4(ax * inv, ay * inv, az * inv, aw * inv);
    *(float4*)(out + (size_t)e*128 + head*8 + half*4) = o;
}

// ---------------- launcher ----------------
extern "C" void kernel_launch(void* const* d_in, const int* in_sizes, int n_in,
                              void* d_out, int out_size)
{
    const float* h_bond = (const float*)d_in[1];
    const float* pos    = (const float*)d_in[2];
    const float* kW1 = (const float*)d_in[3];
    const float* kb1 = (const float*)d_in[4];
    const float* kg  = (const float*)d_in[5];
    const float* kb  = (const float*)d_in[6];
    const float* kW2 = (const float*)d_in[7];
    const float* kb2 = (const float*)d_in[8];
    const float* vW1 = (const float*)d_in[9];
    const float* vb1 = (const float*)d_in[10];
    const float* vg  = (const float*)d_in[11];
    const float* vb  = (const float*)d_in[12];
    const float* vW2 = (const float*)d_in[13];
    const float* vb2 = (const float*)d_in[14];
    const float* qW1 = (const float*)d_in[15];
    const float* qb1 = (const float*)d_in[16];
    const float* qg  = (const float*)d_in[17];
    const float* qb  = (const float*)d_in[18];
    const float* qW2 = (const float*)d_in[19];
    const float* qb2 = (const float*)d_in[20];
    const int* bond_row = (const int*)d_in[21];
    const int* bond_col = (const int*)d_in[22];
    const int* idx_i  = (const int*)d_in[23];
    const int* idx_j  = (const int*)d_in[24];
    const int* idx_k  = (const int*)d_in[25];
    const int* idx_kj = (const int*)d_in[26];
    const int* idx_ji = (const int*)d_in[27];
    int E = in_sizes[21];
    int T = in_sizes[23];

    // triplet smem: Xs(128*196) + KB(3*4096) + VB(3*4096) + red(2*1152) + mus/rss(256) + idx(256)
    const int SMEM_T = (128*196 + 3*4096 + 3*4096 + 2*1152 + 256 + 256) * 4;  // 209,920 B
    const int SMEM_Q = (128*132 + 128*132 + 2*4096 + 2*1152 + 256) * 4;       // 178,176 B
    cudaFuncSetAttribute(q_mlp_kernel,   cudaFuncAttributeMaxDynamicSharedMemorySize, SMEM_Q);
    cudaFuncSetAttribute(triplet_kernel, cudaFuncAttributeMaxDynamicSharedMemorySize, SMEM_T);

    int nb  = (T + 127) / 128;
    int nbA = nb / 2; if (nbA < 1) nbA = 1;
    int nbB = nb - nbA;

    edge_feat_kernel<<<(E + 255) / 256, 256>>>(pos, bond_row, bond_col, E);
    q_mlp_kernel<<<(E + 127) / 128, 256, SMEM_Q>>>(h_bond, qW1, qb1, qg, qb, qW2, qb2, E);
    triplet_kernel<<<nbA, 256, SMEM_T>>>(
        h_bond, pos,
        kW1, kb1, kg, kb, kW2, kb2,
        vW1, vb1, vg, vb, vW2, vb2,
        idx_i, idx_j, idx_k, idx_kj, idx_ji, 0, T);
    if (nbB > 0)
        triplet_kernel<<<nbB, 256, SMEM_T>>>(
            h_bond, pos,
            kW1, kb1, kg, kb, kW2, kb2,
            vW1, vb1, vg, vb, vW2, vb2,
            idx_i, idx_j, idx_k, idx_kj, idx_ji, nbA, T);
    attn_out_kernel<<<(E * 32 + 255) / 256, 256>>>(idx_ji, T, E, (float*)d_out);
}

// round 9
// speedup vs baseline: 1.6054x; 1.0074x over previous
#include <cuda_runtime.h>
#include <math.h>

// ---------------------------------------------------------------------------
// BondUpdateLayer, round 9: 512-thread CTAs (16 warps, 4/SMSP) for latency
// hiding. Warp = 8 output cols (one head), lane = 4 rows @ stride 32.
// Unmerged GEMMs, single 2-buffer cp.async weight ring, Xs kept live.
// Fix vs round 8: SMEM_T allocates the full 256 floats for kjS/jiS.
// ---------------------------------------------------------------------------

#define EN    80000
#define TMAXN 640000
#define NT    512

typedef unsigned long long ull;

__device__ float g_rfeat [EN * 20];
__device__ float g_q     [EN * 128];
__device__ float g_logits[(size_t)TMAXN * 16];
__device__ float g_v     [(size_t)TMAXN * 128];

__device__ __forceinline__ ull pack2(float v) {
    ull r;
    asm("mov.b64 %0, {%1, %1};" : "=l"(r) : "f"(v));
    return r;
}
__device__ __forceinline__ void fma2(ull& d, ull a, ull b) {
    asm("fma.rn.f32x2 %0, %1, %2, %0;" : "+l"(d) : "l"(a), "l"(b));
}
__device__ __forceinline__ float2 unpack2(ull v) {
    float lo, hi;
    asm("mov.b64 {%0, %1}, %2;" : "=f"(lo), "=f"(hi) : "l"(v));
    return make_float2(lo, hi);
}

#define CP_COMMIT() asm volatile("cp.async.commit_group;")
#define CP_WAIT1()  asm volatile("cp.async.wait_group 1;")

// ---- cp.async weight chunk loader (no commit): 32 k-rows x 128 cols ----
__device__ __forceinline__ void load_chunk_nc(const float* __restrict__ W, int kdim,
                                              int c, float* dst, int tid)
{
    #pragma unroll
    for (int i = 0; i < 2; i++) {
        int v = tid + i * NT;             // 0..1023 float4 slots
        int krow = c * 32 + (v >> 5);
        float* d = dst + v * 4;
        if (krow < kdim) {
            unsigned sa = (unsigned)__cvta_generic_to_shared(d);
            const float* s = W + (size_t)krow * 128 + (v & 31) * 4;
            asm volatile("cp.async.cg.shared.global [%0], [%1], 16;" :: "r"(sa), "l"(s));
        } else {
            d[0] = 0.f; d[1] = 0.f; d[2] = 0.f; d[3] = 0.f;
        }
    }
}

// ---- one 32-k GEMM chunk: warp owns 8 cols, lane owns 4 rows @ stride 32 ----
__device__ __forceinline__ void gemm_chunk(const float* __restrict__ Xl, int xstride,
                                           const float* __restrict__ Wp, int w8,
                                           ull acc[4][4])
{
    #pragma unroll
    for (int kq = 0; kq < 8; ++kq) {
        float4 act[4];
        #pragma unroll
        for (int rr = 0; rr < 4; rr++)
            act[rr] = *(const float4*)(Xl + rr * 32 * xstride + kq * 4);
        #pragma unroll
        for (int k4 = 0; k4 < 4; ++k4) {
            const ulonglong2* wp = (const ulonglong2*)(Wp + (kq * 4 + k4) * 128 + w8);
            ulonglong2 wA = wp[0], wB = wp[1];
            #pragma unroll
            for (int rr = 0; rr < 4; rr++) {
                float a = (k4 == 0) ? act[rr].x : (k4 == 1) ? act[rr].y
                        : (k4 == 2) ? act[rr].z : act[rr].w;
                ull ap = pack2(a);
                fma2(acc[rr][0], ap, wA.x);
                fma2(acc[rr][1], ap, wA.y);
                fma2(acc[rr][2], ap, wB.x);
                fma2(acc[rr][3], ap, wB.y);
            }
        }
    }
}

// ---- bias + LayerNorm + ReLU: acc -> Hs (stride 132). 2 internal syncs. ----
__device__ __forceinline__ void ln_relu(ull acc[4][4],
    const float* __restrict__ b1, const float* __restrict__ gam,
    const float* __restrict__ bet,
    float* Hs, float* red, float* mus, float* rss,
    int tid, int l, int w)
{
    const int w8 = w * 8;
    float a1[4][8];
    #pragma unroll
    for (int r = 0; r < 4; r++) {
        float s = 0.f, s2 = 0.f;
        #pragma unroll
        for (int cp = 0; cp < 4; cp++) {
            float2 t = unpack2(acc[r][cp]);
            float x0 = t.x + b1[w8 + cp * 2];
            float x1 = t.y + b1[w8 + cp * 2 + 1];
            a1[r][cp * 2]     = x0;
            a1[r][cp * 2 + 1] = x1;
            s += x0 + x1; s2 += x0 * x0 + x1 * x1;
        }
        int row = r * 32 + l;
        red[row * 17 + w]        = s;
        red[2176 + row * 17 + w] = s2;
    }
    __syncthreads();
    if (tid < 128) {
        float s = 0.f, s2 = 0.f;
        #pragma unroll
        for (int i = 0; i < 16; i++) { s += red[tid * 17 + i]; s2 += red[2176 + tid * 17 + i]; }
        float mu  = s * (1.f / 128.f);
        float var = fmaxf(s2 * (1.f / 128.f) - mu * mu, 0.f);
        mus[tid] = mu;
        rss[tid] = rsqrtf(var + 1e-5f);
    }
    __syncthreads();
    #pragma unroll
    for (int r = 0; r < 4; r++) {
        int row = r * 32 + l;
        float mu = mus[row], rs = rss[row];
        float4 hv[2];
        #pragma unroll
        for (int c = 0; c < 8; c++) {
            float h = gam[w8 + c] * (a1[r][c] - mu) * rs + bet[w8 + c];
            ((float*)hv)[c] = fmaxf(h, 0.f);
        }
        float4* hp = (float4*)(Hs + row * 132 + w8);
        hp[0] = hv[0]; hp[1] = hv[1];
    }
}

// ---- full MLP (512-thread layout). Requires W1 chunks 0,1 already committed.
__device__ __forceinline__ void mlp512(
    const float* __restrict__ Xs, int xstride, int n1, int kdim1,
    const float* __restrict__ b1,
    const float* __restrict__ gam, const float* __restrict__ bet,
    const float* __restrict__ W1,
    const float* __restrict__ W2, const float* __restrict__ b2,
    float* Hs, float* Wb, float* red, float* mus, float* rss,
    int tid, int l, int w, float out[4][8])
{
    const int w8 = w * 8;
    ull a1p[4][4];
    #pragma unroll
    for (int r = 0; r < 4; r++)
        #pragma unroll
        for (int c = 0; c < 4; c++) a1p[r][c] = 0ULL;

    const float* Xl = Xs + l * xstride;

    for (int c = 0; c < n1; c++) {
        CP_WAIT1();
        __syncthreads();
        gemm_chunk(Xl + c * 32, xstride, Wb + (c & 1) * 4096, w8, a1p);
        __syncthreads();
        if (c + 2 < n1) load_chunk_nc(W1, kdim1, c + 2, Wb + (c & 1) * 4096, tid);
        CP_COMMIT();
    }
    load_chunk_nc(W2, 128, 0, Wb + 0,    tid); CP_COMMIT();
    load_chunk_nc(W2, 128, 1, Wb + 4096, tid); CP_COMMIT();

    ln_relu(a1p, b1, gam, bet, Hs, red, mus, rss, tid, l, w);

    ull a2p[4][4];
    #pragma unroll
    for (int r = 0; r < 4; r++)
        #pragma unroll
        for (int c = 0; c < 4; c++) a2p[r][c] = 0ULL;

    const float* Hl = Hs + l * 132;
    for (int c = 0; c < 4; c++) {
        CP_WAIT1();
        __syncthreads();
        gemm_chunk(Hl + c * 32, 132, Wb + (c & 1) * 4096, w8, a2p);
        __syncthreads();
        if (c + 2 < 4) load_chunk_nc(W2, 128, c + 2, Wb + (c & 1) * 4096, tid);
        CP_COMMIT();
    }
    #pragma unroll
    for (int r = 0; r < 4; r++)
        #pragma unroll
        for (int cp = 0; cp < 4; cp++) {
            float2 t = unpack2(a2p[r][cp]);
            out[r][cp * 2]     = t.x + b2[w8 + cp * 2];
            out[r][cp * 2 + 1] = t.y + b2[w8 + cp * 2 + 1];
        }
}

// ---------------- K1a: edge gaussian features ----------------
__global__ void edge_feat_kernel(const float* __restrict__ pos,
                                 const int* __restrict__ brow,
                                 const int* __restrict__ bcol, int E)
{
    int e = blockIdx.x * blockDim.x + threadIdx.x;
    if (e >= E) return;
    int r = brow[e], c = bcol[e];
    float dx = pos[c*3+0] - pos[r*3+0];
    float dy = pos[c*3+1] - pos[r*3+1];
    float dz = pos[c*3+2] - pos[r*3+2];
    float d  = sqrtf(dx*dx + dy*dy + dz*dz);
    const float step  = 10.0f / 19.0f;
    const float coeff = -0.5f / (step * step);
    #pragma unroll
    for (int g = 0; g < 20; ++g) {
        float t = d - step * (float)g;
        g_rfeat[e*20 + g] = expf(coeff * t * t);
    }
}

// ---------------- K1b: Q MLP over edges ----------------
__global__ void __launch_bounds__(NT, 1) q_mlp_kernel(const float* __restrict__ h_bond,
    const float* __restrict__ W1, const float* __restrict__ b1,
    const float* __restrict__ gam, const float* __restrict__ bet,
    const float* __restrict__ W2, const float* __restrict__ b2, int E)
{
    extern __shared__ float sm[];
    float* Xs  = sm;                   // 128*132
    float* Hs  = Xs + 128*132;         // 128*132
    float* Wb  = Hs + 128*132;         // 2*4096
    float* red = Wb + 2*4096;          // 2*2176
    float* mus = red + 2*2176;         // 128
    float* rss = mus + 128;            // 128
    int tid = threadIdx.x, l = tid & 31, w = tid >> 5;
    int e0 = blockIdx.x * 128;

    load_chunk_nc(W1, 128, 0, Wb + 0,    tid); CP_COMMIT();
    load_chunk_nc(W1, 128, 1, Wb + 4096, tid); CP_COMMIT();

    for (int v = tid; v < 128*32; v += NT) {
        int row = v >> 5, c4 = v & 31;
        float4 x = make_float4(0.f, 0.f, 0.f, 0.f);
        if (e0 + row < E) x = ((const float4*)h_bond)[(size_t)(e0 + row)*32 + c4];
        float* xr = Xs + row*132 + c4*4;
        xr[0] = x.x; xr[1] = x.y; xr[2] = x.z; xr[3] = x.w;
    }

    float out[4][8];
    mlp512(Xs, 132, 4, 128, b1, gam, bet, W1, W2, b2,
           Hs, Wb, red, mus, rss, tid, l, w, out);

    #pragma unroll
    for (int r = 0; r < 4; r++) {
        int row = r * 32 + l;
        int e = e0 + row;
        if (e < E) {
            float4* qp = (float4*)(g_q + (size_t)e*128 + w*8);
            qp[0] = *(float4*)&out[r][0];
            qp[1] = *(float4*)&out[r][4];
        }
    }
}

// ---------------- K2: triplet kv -> hk (logits), hv (V) ----------------
__global__ void __launch_bounds__(NT, 1) triplet_kernel(
    const float* __restrict__ h_bond, const float* __restrict__ pos,
    const float* __restrict__ kW1, const float* __restrict__ kb1,
    const float* __restrict__ kg,  const float* __restrict__ kb,
    const float* __restrict__ kW2, const float* __restrict__ kb2,
    const float* __restrict__ vW1, const float* __restrict__ vb1,
    const float* __restrict__ vg,  const float* __restrict__ vb,
    const float* __restrict__ vW2, const float* __restrict__ vb2,
    const int* __restrict__ idx_i, const int* __restrict__ idx_j,
    const int* __restrict__ idx_k, const int* __restrict__ idx_kj,
    const int* __restrict__ idx_ji, int blk0, int T)
{
    extern __shared__ float sm[];
    const int XS = 196;                 // 192 data cols + 4 pad (== 4 mod 32)
    float* Xs  = sm;                    // 128*196 (stays live for both MLPs)
    float* Hs  = Xs + 128*XS;           // 128*132
    float* Wb  = Hs + 128*132;          // 2*4096
    float* red = Wb + 2*4096;           // 2*2176
    float* mus = red + 2*2176;          // 128
    float* rss = mus + 128;             // 128
    int*   kjS = (int*)(rss + 128);     // 128
    int*   jiS = kjS + 128;             // 128

    int tid = threadIdx.x, l = tid & 31, w = tid >> 5;
    const int w8 = w * 8;
    int t0 = (blockIdx.x + blk0) * 128;

    // prefetch hk W1 chunks 0,1 (overlaps assembly)
    load_chunk_nc(kW1, 181, 0, Wb + 0,    tid); CP_COMMIT();
    load_chunk_nc(kW1, 181, 1, Wb + 4096, tid); CP_COMMIT();

    // zero tail cols 176..195
    for (int v = tid; v < 128*5; v += NT) {
        int row = v / 5, c4 = v % 5;
        ((float4*)(Xs + row*XS + 176))[c4] = make_float4(0.f, 0.f, 0.f, 0.f);
    }
    __syncthreads();

    // per-row indices + angular features (cols 168..180)
    if (tid < 128) {
        int t = t0 + tid;
        if (t < T) {
            int kj = idx_kj[t], ji = idx_ji[t];
            kjS[tid] = kj; jiS[tid] = ji;
            int ii = idx_i[t], jj = idx_j[t], kk = idx_k[t];
            float pix = pos[ii*3+0], piy = pos[ii*3+1], piz = pos[ii*3+2];
            float jx = pos[jj*3+0]-pix, jy = pos[jj*3+1]-piy, jz = pos[jj*3+2]-piz;
            float kx = pos[kk*3+0]-pix, ky = pos[kk*3+1]-piy, kz = pos[kk*3+2]-piz;
            float dt = jx*kx + jy*ky + jz*kz;
            float cx = jy*kz - jz*ky, cy = jz*kx - jx*kz, cz = jx*ky - jy*kx;
            float cr = sqrtf(cx*cx + cy*cy + cz*cz);
            float ang = atan2f(cr, dt);
            float* xr = Xs + tid*XS + 168;
            xr[0] = ang;
            const float fq[6] = {1.f, 2.f, 3.f, 1.f, 0.5f, 1.f/3.f};
            #pragma unroll
            for (int i = 0; i < 6; i++) {
                xr[1 + i] = sinf(ang * fq[i]);
                xr[7 + i] = cosf(ang * fq[i]);
            }
        } else {
            kjS[tid] = -1; jiS[tid] = -1;
            float* xr = Xs + tid*XS;
            #pragma unroll
            for (int c4 = 0; c4 < 44; c4++)
                ((float4*)xr)[c4] = make_float4(0.f, 0.f, 0.f, 0.f);
        }
    }
    __syncthreads();

    // h_bond[idx_kj] gather -> cols 0..127
    for (int v = tid; v < 128*32; v += NT) {
        int row = v >> 5, c4 = v & 31;
        int kj = kjS[row];
        if (kj >= 0) {
            float4 hb = ((const float4*)h_bond)[(size_t)kj*32 + c4];
            float* xr = Xs + row*XS + c4*4;
            xr[0] = hb.x; xr[1] = hb.y; xr[2] = hb.z; xr[3] = hb.w;
        }
    }
    // rfeat gathers -> cols 128..147 (kj), 148..167 (ji)
    for (int v = tid; v < 128*20; v += NT) {
        int row = v / 20, g = v % 20;
        int kj = kjS[row];
        if (kj >= 0) {
            Xs[row*XS + 128 + g] = g_rfeat[kj*20 + g];
            Xs[row*XS + 148 + g] = g_rfeat[jiS[row]*20 + g];
        }
    }

    // -------- hk MLP --------
    float out[4][8];
    mlp512(Xs, XS, 6, 181, kb1, kg, kb, kW1, kW2, kb2,
           Hs, Wb, red, mus, rss, tid, l, w, out);

    // prefetch hv W1 (overlaps logits epilogue)
    load_chunk_nc(vW1, 181, 0, Wb + 0,    tid); CP_COMMIT();
    load_chunk_nc(vW1, 181, 1, Wb + 4096, tid); CP_COMMIT();

    // -------- logits epilogue (warp w == head w) --------
    const float scale = 0.3535533905932738f;  // 1/sqrt(8)
    #pragma unroll
    for (int r = 0; r < 4; r++) {
        int row = r * 32 + l;
        int ji = jiS[row];
        if (ji >= 0) {
            const float4* qp = (const float4*)(g_q + (size_t)ji*128 + w8);
            float4 q0 = qp[0], q1 = qp[1];
            float lg = out[r][0]*q0.x + out[r][1]*q0.y + out[r][2]*q0.z + out[r][3]*q0.w
                     + out[r][4]*q1.x + out[r][5]*q1.y + out[r][6]*q1.z + out[r][7]*q1.w;
            g_logits[(size_t)(t0 + row)*16 + w] = lg * scale;
        }
    }

    // -------- hv MLP (Xs still live) --------
    mlp512(Xs, XS, 6, 181, vb1, vg, vb, vW1, vW2, vb2,
           Hs, Wb, red, mus, rss, tid, l, w, out);

    #pragma unroll
    for (int r = 0; r < 4; r++) {
        int row = r * 32 + l;
        if (jiS[row] >= 0) {
            float4* vp = (float4*)(g_v + (size_t)(t0 + row)*128 + w8);
            vp[0] = *(float4*)&out[r][0];
            vp[1] = *(float4*)&out[r][4];
        }
    }
}

// ---------------- K3: per-edge segment softmax + weighted V sum ----------------
__global__ void attn_out_kernel(const int* __restrict__ idx_ji,
                                int T, int E, float* __restrict__ out)
{
    int warp = (blockIdx.x * blockDim.x + threadIdx.x) >> 5;
    int lane = threadIdx.x & 31;
    if (warp >= E) return;
    int e = warp;

    int lo = 0, hi = T;
    while (lo < hi) { int m = (lo + hi) >> 1; if (idx_ji[m] <  e)     lo = m + 1; else hi = m; }
    int s = lo;
    int hi2 = T;
    while (lo < hi2) { int m = (lo + hi2) >> 1; if (idx_ji[m] < e + 1) lo = m + 1; else hi2 = m; }
    int en = lo;

    int head = lane >> 1, half = lane & 1;

    float mx = -INFINITY;
    for (int t = s; t < en; t++) mx = fmaxf(mx, g_logits[(size_t)t*16 + head]);

    float den = 0.f;
    float ax = 0.f, ay = 0.f, az = 0.f, aw = 0.f;
    for (int t = s; t < en; t++) {
        float w = expf(g_logits[(size_t)t*16 + head] - mx);
        den += w;
        float4 v = *(const float4*)(g_v + (size_t)t*128 + head*8 + half*4);
        ax += w * v.x; ay += w * v.y; az += w * v.z; aw += w * v.w;
    }
    float inv = (en > s) ? (1.f / den) : 0.f;
    float4 o = make_float4(ax * inv, ay * inv, az * inv, aw * inv);
    *(float4*)(out + (size_t)e*128 + head*8 + half*4) = o;
}

// ---------------- launcher ----------------
extern "C" void kernel_launch(void* const* d_in, const int* in_sizes, int n_in,
                              void* d_out, int out_size)
{
    const float* h_bond = (const float*)d_in[1];
    const float* pos    = (const float*)d_in[2];
    const float* kW1 = (const float*)d_in[3];
    const float* kb1 = (const float*)d_in[4];
    const float* kg  = (const float*)d_in[5];
    const float* kb  = (const float*)d_in[6];
    const float* kW2 = (const float*)d_in[7];
    const float* kb2 = (const float*)d_in[8];
    const float* vW1 = (const float*)d_in[9];
    const float* vb1 = (const float*)d_in[10];
    const float* vg  = (const float*)d_in[11];
    const float* vb  = (const float*)d_in[12];
    const float* vW2 = (const float*)d_in[13];
    const float* vb2 = (const float*)d_in[14];
    const float* qW1 = (const float*)d_in[15];
    const float* qb1 = (const float*)d_in[16];
    const float* qg  = (const float*)d_in[17];
    const float* qb  = (const float*)d_in[18];
    const float* qW2 = (const float*)d_in[19];
    const float* qb2 = (const float*)d_in[20];
    const int* bond_row = (const int*)d_in[21];
    const int* bond_col = (const int*)d_in[22];
    const int* idx_i  = (const int*)d_in[23];
    const int* idx_j  = (const int*)d_in[24];
    const int* idx_k  = (const int*)d_in[25];
    const int* idx_kj = (const int*)d_in[26];
    const int* idx_ji = (const int*)d_in[27];
    int E = in_sizes[21];
    int T = in_sizes[23];

    // triplet smem: Xs(128*196) + Hs(128*132) + Wb(2*4096) + red(2*2176)
    //             + mus/rss(256) + kjS/jiS(256)
    const int SMEM_T = (128*196 + 128*132 + 2*4096 + 2*2176 + 256 + 256) * 4; // 220,160 B
    const int SMEM_Q = (128*132 + 128*132 + 2*4096 + 2*2176 + 256) * 4;       // 186,368 B
    cudaFuncSetAttribute(q_mlp_kernel,   cudaFuncAttributeMaxDynamicSharedMemorySize, SMEM_Q);
    cudaFuncSetAttribute(triplet_kernel, cudaFuncAttributeMaxDynamicSharedMemorySize, SMEM_T);

    int nb  = (T + 127) / 128;
    int nbA = nb / 2; if (nbA < 1) nbA = 1;
    int nbB = nb - nbA;

    edge_feat_kernel<<<(E + 255) / 256, 256>>>(pos, bond_row, bond_col, E);
    q_mlp_kernel<<<(E + 127) / 128, NT, SMEM_Q>>>(h_bond, qW1, qb1, qg, qb, qW2, qb2, E);
    triplet_kernel<<<nbA, NT, SMEM_T>>>(
        h_bond, pos,
        kW1, kb1, kg, kb, kW2, kb2,
        vW1, vb1, vg, vb, vW2, vb2,
        idx_i, idx_j, idx_k, idx_kj, idx_ji, 0, T);
    if (nbB > 0)
        triplet_kernel<<<nbB, NT, SMEM_T>>>(
            h_bond, pos,
            kW1, kb1, kg, kb, kW2, kb2,
            vW1, vb1, vg, vb, vW2, vb2,
            idx_i, idx_j, idx_k, idx_kj, idx_ji, nbA, T);
    attn_out_kernel<<<(E * 32 + 255) / 256, 256>>>(idx_ji, T, E, (float*)d_out);
}